// round 2
// baseline (speedup 1.0000x reference)
#include <cuda_runtime.h>
#include <cuda_bf16.h>
#include <cstdint>

// Problem constants (fixed by the reference)
#define N_NODES 100000
#define N_EDGES 1600000
#define F_IN  128
#define F_MID 128
#define F_OUT 64

// Scratch (static device globals; runtime allocation is forbidden)
__device__ __align__(16) float d_deg [N_NODES];
__device__ __align__(16) float d_dinv[N_NODES];
__device__ __align__(16) float d_g1  [(size_t)N_NODES * F_MID];  // (x@W1)*dinv[row]
__device__ __align__(16) float d_acc1[(size_t)N_NODES * F_MID];  // segment-sum accumulator L1
__device__ __align__(16) float d_g2  [(size_t)N_NODES * F_OUT];  // (h@W2)*dinv[row]

// ---------------------------------------------------------------------------
// Degree / normalization.  NOTE: edge_index is int32 on device (JAX default
// x64-disabled silently downgrades jnp.int64 -> int32).
// ---------------------------------------------------------------------------
__global__ void init_deg_kernel() {
    int i = blockIdx.x * blockDim.x + threadIdx.x;
    if (i < N_NODES) d_deg[i] = 1.0f;  // self-loop contributes 1
}

__global__ void count_deg_kernel(const int* __restrict__ ei) {
    int e = blockIdx.x * blockDim.x + threadIdx.x;
    if (e < N_EDGES) {
        int c = ei[N_EDGES + e];  // cols
        atomicAdd(&d_deg[c], 1.0f);
    }
}

__global__ void dinv_kernel() {
    int i = blockIdx.x * blockDim.x + threadIdx.x;
    if (i < N_NODES) d_dinv[i] = rsqrtf(d_deg[i]);  // deg >= 1 always
}

// ---------------------------------------------------------------------------
// GEMM1: g1[i][:] = (x[i][:] @ W1) * dinv[i];  acc1 = g1 (self-loop init)
// Block = 256 threads = 8 warps; warp handles 4 rows; lane handles 4 cols.
// 100000 rows = 3125 blocks * 32 rows, exact.
// ---------------------------------------------------------------------------
__global__ void __launch_bounds__(256) gemm1_kernel(const float* __restrict__ x,
                                                    const float* __restrict__ W1) {
    __shared__ float xs[8][4][F_IN];
    const int w = threadIdx.x >> 5, lane = threadIdx.x & 31;
    const int rowbase = blockIdx.x * 32 + w * 4;

    #pragma unroll
    for (int r = 0; r < 4; r++) {
        int row = rowbase + r;
        float4 v = reinterpret_cast<const float4*>(x + (size_t)row * F_IN)[lane];
        *reinterpret_cast<float4*>(&xs[w][r][lane * 4]) = v;
    }
    __syncwarp();

    float4 acc[4] = {};
    const float4* W4 = reinterpret_cast<const float4*>(W1);
    #pragma unroll 4
    for (int k = 0; k < F_IN; k++) {
        float4 wv = W4[k * (F_MID / 4) + lane];
        #pragma unroll
        for (int r = 0; r < 4; r++) {
            float xv = xs[w][r][k];
            acc[r].x = fmaf(wv.x, xv, acc[r].x);
            acc[r].y = fmaf(wv.y, xv, acc[r].y);
            acc[r].z = fmaf(wv.z, xv, acc[r].z);
            acc[r].w = fmaf(wv.w, xv, acc[r].w);
        }
    }

    #pragma unroll
    for (int r = 0; r < 4; r++) {
        int row = rowbase + r;
        float s = d_dinv[row];
        float4 o = make_float4(acc[r].x * s, acc[r].y * s, acc[r].z * s, acc[r].w * s);
        reinterpret_cast<float4*>(d_g1   + (size_t)row * F_MID)[lane] = o;
        reinterpret_cast<float4*>(d_acc1 + (size_t)row * F_MID)[lane] = o;
    }
}

// ---------------------------------------------------------------------------
// Scatter layer 1: warp per edge, 128 floats = 32 lanes x float4
// acc1[col] += g1[row]  via red.global.add.v4.f32 (vector reduction, sm_90+)
// ---------------------------------------------------------------------------
__global__ void __launch_bounds__(256) scatter1_kernel(const int* __restrict__ ei) {
    int wid  = (blockIdx.x * blockDim.x + threadIdx.x) >> 5;
    int lane = threadIdx.x & 31;
    if (wid >= N_EDGES) return;
    int r = ei[wid];
    int c = ei[N_EDGES + wid];
    float4 v = reinterpret_cast<const float4*>(d_g1 + (size_t)r * F_MID)[lane];
    float* dst = d_acc1 + (size_t)c * F_MID + lane * 4;
    asm volatile("red.global.add.v4.f32 [%0], {%1, %2, %3, %4};"
                 :: "l"(dst), "f"(v.x), "f"(v.y), "f"(v.z), "f"(v.w) : "memory");
}

// ---------------------------------------------------------------------------
// Layer 2 fused: h = relu(dinv*acc1 + b1); g2 = (h @ W2) * dinv; d_out = g2
// Same 8-warp/4-row layout; lane handles 2 output cols (F_OUT=64).
// ---------------------------------------------------------------------------
__global__ void __launch_bounds__(256) layer2_kernel(const float* __restrict__ b1,
                                                     const float* __restrict__ W2,
                                                     float* __restrict__ out) {
    __shared__ float hs[8][4][F_MID];
    const int w = threadIdx.x >> 5, lane = threadIdx.x & 31;
    const int rowbase = blockIdx.x * 32 + w * 4;

    float4 bv = reinterpret_cast<const float4*>(b1)[lane];
    #pragma unroll
    for (int r = 0; r < 4; r++) {
        int row = rowbase + r;
        float s = d_dinv[row];
        float4 v = reinterpret_cast<const float4*>(d_acc1 + (size_t)row * F_MID)[lane];
        v.x = fmaxf(fmaf(v.x, s, bv.x), 0.0f);
        v.y = fmaxf(fmaf(v.y, s, bv.y), 0.0f);
        v.z = fmaxf(fmaf(v.z, s, bv.z), 0.0f);
        v.w = fmaxf(fmaf(v.w, s, bv.w), 0.0f);
        *reinterpret_cast<float4*>(&hs[w][r][lane * 4]) = v;
    }
    __syncwarp();

    float2 acc[4] = {};
    const float2* W2v = reinterpret_cast<const float2*>(W2);
    #pragma unroll 4
    for (int k = 0; k < F_MID; k++) {
        float2 wv = W2v[k * (F_OUT / 2) + lane];
        #pragma unroll
        for (int r = 0; r < 4; r++) {
            float xv = hs[w][r][k];
            acc[r].x = fmaf(wv.x, xv, acc[r].x);
            acc[r].y = fmaf(wv.y, xv, acc[r].y);
        }
    }

    #pragma unroll
    for (int r = 0; r < 4; r++) {
        int row = rowbase + r;
        float s = d_dinv[row];
        float2 o = make_float2(acc[r].x * s, acc[r].y * s);
        reinterpret_cast<float2*>(d_g2 + (size_t)row * F_OUT)[lane] = o;
        reinterpret_cast<float2*>(out  + (size_t)row * F_OUT)[lane] = o;
    }
}

// ---------------------------------------------------------------------------
// Scatter layer 2: half-warp per edge, 64 floats = 16 x float4
// ---------------------------------------------------------------------------
__global__ void __launch_bounds__(256) scatter2_kernel(const int* __restrict__ ei,
                                                       float* __restrict__ out) {
    int t   = blockIdx.x * blockDim.x + threadIdx.x;
    int e   = t >> 4;
    int sub = t & 15;
    if (e >= N_EDGES) return;
    int r = ei[e];
    int c = ei[N_EDGES + e];
    float4 v = reinterpret_cast<const float4*>(d_g2 + (size_t)r * F_OUT)[sub];
    float* dst = out + (size_t)c * F_OUT + sub * 4;
    asm volatile("red.global.add.v4.f32 [%0], {%1, %2, %3, %4};"
                 :: "l"(dst), "f"(v.x), "f"(v.y), "f"(v.z), "f"(v.w) : "memory");
}

// ---------------------------------------------------------------------------
// Finalize: out = dinv*out + b2 (elementwise over 100000 x 64)
// ---------------------------------------------------------------------------
__global__ void __launch_bounds__(256) finalize2_kernel(float* __restrict__ out,
                                                        const float* __restrict__ b2) {
    int t = blockIdx.x * blockDim.x + threadIdx.x;  // index over float4s
    if (t >= N_NODES * (F_OUT / 4)) return;
    int row = t >> 4;
    int c4  = t & 15;
    float s = d_dinv[row];
    float4 v = reinterpret_cast<float4*>(out)[t];
    float4 b = reinterpret_cast<const float4*>(b2)[c4];
    v.x = fmaf(v.x, s, b.x);
    v.y = fmaf(v.y, s, b.y);
    v.z = fmaf(v.z, s, b.z);
    v.w = fmaf(v.w, s, b.w);
    reinterpret_cast<float4*>(out)[t] = v;
}

// ---------------------------------------------------------------------------
// Launch
// Inputs (metadata order): x, edge_index(int32!), edge_weight, W1, b1, W2, b2
// ---------------------------------------------------------------------------
extern "C" void kernel_launch(void* const* d_in, const int* in_sizes, int n_in,
                              void* d_out, int out_size) {
    const float* x  = (const float*)d_in[0];
    const int*   ei = (const int*)d_in[1];
    // d_in[2] = edge_weight: ignored (reference overwrites weights with ones)
    const float* W1 = (const float*)d_in[3];
    const float* b1 = (const float*)d_in[4];
    const float* W2 = (const float*)d_in[5];
    const float* b2 = (const float*)d_in[6];
    float* out = (float*)d_out;

    // 1) degree + dinv
    init_deg_kernel<<<(N_NODES + 255) / 256, 256>>>();
    count_deg_kernel<<<(N_EDGES + 255) / 256, 256>>>(ei);
    dinv_kernel<<<(N_NODES + 255) / 256, 256>>>();

    // 2) g1 = (x@W1)*dinv ; acc1 = g1
    gemm1_kernel<<<N_NODES / 32, 256>>>(x, W1);   // 3125 blocks exactly

    // 3) acc1[col] += g1[row] over edges
    scatter1_kernel<<<(N_EDGES * 32 + 255) / 256, 256>>>(ei);

    // 4) h = relu(dinv*acc1+b1); g2 = (h@W2)*dinv; out = g2
    layer2_kernel<<<N_NODES / 32, 256>>>(b1, W2, out);

    // 5) out[col] += g2[row] over edges
    scatter2_kernel<<<(N_EDGES * 16 + 255) / 256, 256>>>(ei, out);

    // 6) out = dinv*out + b2
    finalize2_kernel<<<(N_NODES * (F_OUT / 4) + 255) / 256, 256>>>(out, b2);
}

// round 3
// speedup vs baseline: 1.5938x; 1.5938x over previous
#include <cuda_runtime.h>
#include <cuda_bf16.h>
#include <cstdint>

#define N_NODES 100000
#define N_EDGES 1600000
#define F_IN  128
#define F_MID 128
#define F_OUT 64

#define SCAN_BLK 512
#define N_SCAN_BLKS ((N_NODES + SCAN_BLK - 1) / SCAN_BLK)   // 196

// Scratch (static device globals; runtime allocation is forbidden)
__device__ __align__(16) int   d_deg_i[N_NODES];
__device__ __align__(16) int   d_fill [N_NODES];
__device__ __align__(16) int   d_ptr  [N_NODES];
__device__ __align__(16) int   d_bsum [N_SCAN_BLKS];
__device__ __align__(16) int   d_boff [N_SCAN_BLKS];
__device__ __align__(16) int   d_csr  [N_EDGES];
__device__ __align__(16) float d_dinv [N_NODES];
__device__ __align__(16) float d_g1   [(size_t)N_NODES * F_MID];  // (x@W1)*dinv[row]
__device__ __align__(16) float d_h    [(size_t)N_NODES * F_MID];  // relu(layer1 out)
__device__ __align__(16) float d_g2   [(size_t)N_NODES * F_OUT];  // (h@W2)*dinv[row]

// ---------------------------------------------------------------------------
// Degree / CSR build.  edge_index is int32 on device (JAX x64-disabled).
// ---------------------------------------------------------------------------
__global__ void init_kernel() {
    int i = blockIdx.x * blockDim.x + threadIdx.x;
    if (i < N_NODES) { d_deg_i[i] = 0; d_fill[i] = 0; }
}

__global__ void count_deg_kernel(const int* __restrict__ ei) {
    int e = blockIdx.x * blockDim.x + threadIdx.x;
    if (e < N_EDGES) atomicAdd(&d_deg_i[ei[N_EDGES + e]], 1);
}

__global__ void dinv_kernel() {
    int i = blockIdx.x * blockDim.x + threadIdx.x;
    if (i < N_NODES) d_dinv[i] = rsqrtf((float)(1 + d_deg_i[i]));  // +1 self loop
}

// Exclusive prefix scan of deg_i -> ptr, in 3 stages.
__global__ void scan1_kernel() {
    __shared__ int sm[SCAN_BLK];
    int tid = threadIdx.x;
    int i = blockIdx.x * SCAN_BLK + tid;
    int v = (i < N_NODES) ? d_deg_i[i] : 0;
    sm[tid] = v;
    __syncthreads();
    #pragma unroll
    for (int off = 1; off < SCAN_BLK; off <<= 1) {
        int t = (tid >= off) ? sm[tid - off] : 0;
        __syncthreads();
        if (tid >= off) sm[tid] += t;
        __syncthreads();
    }
    if (i < N_NODES) d_ptr[i] = sm[tid] - v;       // exclusive
    if (tid == SCAN_BLK - 1) d_bsum[blockIdx.x] = sm[tid];
}

__global__ void scan2_kernel() {
    __shared__ int sm[256];
    int tid = threadIdx.x;
    int v = (tid < N_SCAN_BLKS) ? d_bsum[tid] : 0;
    sm[tid] = v;
    __syncthreads();
    #pragma unroll
    for (int off = 1; off < 256; off <<= 1) {
        int t = (tid >= off) ? sm[tid - off] : 0;
        __syncthreads();
        if (tid >= off) sm[tid] += t;
        __syncthreads();
    }
    if (tid < N_SCAN_BLKS) d_boff[tid] = sm[tid] - v;  // exclusive
}

__global__ void scan3_kernel() {
    int i = blockIdx.x * SCAN_BLK + threadIdx.x;
    if (i < N_NODES) d_ptr[i] += d_boff[blockIdx.x];
}

__global__ void fill_csr_kernel(const int* __restrict__ ei) {
    int e = blockIdx.x * blockDim.x + threadIdx.x;
    if (e < N_EDGES) {
        int r = ei[e];
        int c = ei[N_EDGES + e];
        int slot = atomicAdd(&d_fill[c], 1);
        d_csr[d_ptr[c] + slot] = r;
    }
}

// ---------------------------------------------------------------------------
// GEMM1: g1[i][:] = (x[i][:] @ W1) * dinv[i]
// 256 threads = 8 warps; warp handles 8 rows; lane handles 4 cols.
// ---------------------------------------------------------------------------
__global__ void __launch_bounds__(256) gemm1_kernel(const float* __restrict__ x,
                                                    const float* __restrict__ W1) {
    __shared__ float xs[8][8][F_IN];
    const int w = threadIdx.x >> 5, lane = threadIdx.x & 31;
    const int rowbase = blockIdx.x * 64 + w * 8;

    #pragma unroll
    for (int r = 0; r < 8; r++) {
        int row = rowbase + r;
        if (row < N_NODES) {
            float4 v = reinterpret_cast<const float4*>(x + (size_t)row * F_IN)[lane];
            *reinterpret_cast<float4*>(&xs[w][r][lane * 4]) = v;
        }
    }
    __syncwarp();

    float4 acc[8] = {};
    const float4* W4 = reinterpret_cast<const float4*>(W1);
    #pragma unroll 2
    for (int k = 0; k < F_IN; k++) {
        float4 wv = W4[k * (F_MID / 4) + lane];
        #pragma unroll
        for (int r = 0; r < 8; r++) {
            float xv = xs[w][r][k];
            acc[r].x = fmaf(wv.x, xv, acc[r].x);
            acc[r].y = fmaf(wv.y, xv, acc[r].y);
            acc[r].z = fmaf(wv.z, xv, acc[r].z);
            acc[r].w = fmaf(wv.w, xv, acc[r].w);
        }
    }

    #pragma unroll
    for (int r = 0; r < 8; r++) {
        int row = rowbase + r;
        if (row < N_NODES) {
            float s = d_dinv[row];
            float4 o = make_float4(acc[r].x * s, acc[r].y * s, acc[r].z * s, acc[r].w * s);
            reinterpret_cast<float4*>(d_g1 + (size_t)row * F_MID)[lane] = o;
        }
    }
}

// ---------------------------------------------------------------------------
// Gather layer 1: warp per node.  h[c] = relu(dinv[c]*(g1[c] + sum_in g1[r]) + b1)
// ---------------------------------------------------------------------------
__global__ void __launch_bounds__(256) gather1_kernel(const float* __restrict__ b1) {
    int node = (blockIdx.x * blockDim.x + threadIdx.x) >> 5;
    int lane = threadIdx.x & 31;
    if (node >= N_NODES) return;
    int s = d_ptr[node];
    int n = d_deg_i[node];

    float4 acc = reinterpret_cast<const float4*>(d_g1 + (size_t)node * F_MID)[lane];
    int i = 0;
    for (; i + 4 <= n; i += 4) {
        int r0 = d_csr[s + i], r1 = d_csr[s + i + 1];
        int r2 = d_csr[s + i + 2], r3 = d_csr[s + i + 3];
        float4 v0 = reinterpret_cast<const float4*>(d_g1 + (size_t)r0 * F_MID)[lane];
        float4 v1 = reinterpret_cast<const float4*>(d_g1 + (size_t)r1 * F_MID)[lane];
        float4 v2 = reinterpret_cast<const float4*>(d_g1 + (size_t)r2 * F_MID)[lane];
        float4 v3 = reinterpret_cast<const float4*>(d_g1 + (size_t)r3 * F_MID)[lane];
        acc.x += v0.x + v1.x + v2.x + v3.x;
        acc.y += v0.y + v1.y + v2.y + v3.y;
        acc.z += v0.z + v1.z + v2.z + v3.z;
        acc.w += v0.w + v1.w + v2.w + v3.w;
    }
    for (; i < n; i++) {
        int r = d_csr[s + i];
        float4 v = reinterpret_cast<const float4*>(d_g1 + (size_t)r * F_MID)[lane];
        acc.x += v.x; acc.y += v.y; acc.z += v.z; acc.w += v.w;
    }

    float sc = d_dinv[node];
    float4 b = reinterpret_cast<const float4*>(b1)[lane];
    float4 o;
    o.x = fmaxf(fmaf(acc.x, sc, b.x), 0.0f);
    o.y = fmaxf(fmaf(acc.y, sc, b.y), 0.0f);
    o.z = fmaxf(fmaf(acc.z, sc, b.z), 0.0f);
    o.w = fmaxf(fmaf(acc.w, sc, b.w), 0.0f);
    reinterpret_cast<float4*>(d_h + (size_t)node * F_MID)[lane] = o;
}

// ---------------------------------------------------------------------------
// GEMM2: g2[i][:] = (h[i][:] @ W2) * dinv[i]   (F_OUT = 64, lane handles 2 cols)
// ---------------------------------------------------------------------------
__global__ void __launch_bounds__(256) gemm2_kernel(const float* __restrict__ W2) {
    __shared__ float hs[8][8][F_MID];
    const int w = threadIdx.x >> 5, lane = threadIdx.x & 31;
    const int rowbase = blockIdx.x * 64 + w * 8;

    #pragma unroll
    for (int r = 0; r < 8; r++) {
        int row = rowbase + r;
        if (row < N_NODES) {
            float4 v = reinterpret_cast<const float4*>(d_h + (size_t)row * F_MID)[lane];
            *reinterpret_cast<float4*>(&hs[w][r][lane * 4]) = v;
        }
    }
    __syncwarp();

    float2 acc[8] = {};
    const float2* W2v = reinterpret_cast<const float2*>(W2);
    #pragma unroll 2
    for (int k = 0; k < F_MID; k++) {
        float2 wv = W2v[k * (F_OUT / 2) + lane];
        #pragma unroll
        for (int r = 0; r < 8; r++) {
            float xv = hs[w][r][k];
            acc[r].x = fmaf(wv.x, xv, acc[r].x);
            acc[r].y = fmaf(wv.y, xv, acc[r].y);
        }
    }

    #pragma unroll
    for (int r = 0; r < 8; r++) {
        int row = rowbase + r;
        if (row < N_NODES) {
            float s = d_dinv[row];
            float2 o = make_float2(acc[r].x * s, acc[r].y * s);
            reinterpret_cast<float2*>(d_g2 + (size_t)row * F_OUT)[lane] = o;
        }
    }
}

// ---------------------------------------------------------------------------
// Gather layer 2: half-warp per node.  out[c] = dinv[c]*(g2[c] + sum_in g2[r]) + b2
// ---------------------------------------------------------------------------
__global__ void __launch_bounds__(256) gather2_kernel(const float* __restrict__ b2,
                                                      float* __restrict__ out) {
    int t = blockIdx.x * blockDim.x + threadIdx.x;
    int node = t >> 4;
    int sub = t & 15;
    if (node >= N_NODES) return;
    int s = d_ptr[node];
    int n = d_deg_i[node];

    float4 acc = reinterpret_cast<const float4*>(d_g2 + (size_t)node * F_OUT)[sub];
    int i = 0;
    for (; i + 4 <= n; i += 4) {
        int r0 = d_csr[s + i], r1 = d_csr[s + i + 1];
        int r2 = d_csr[s + i + 2], r3 = d_csr[s + i + 3];
        float4 v0 = reinterpret_cast<const float4*>(d_g2 + (size_t)r0 * F_OUT)[sub];
        float4 v1 = reinterpret_cast<const float4*>(d_g2 + (size_t)r1 * F_OUT)[sub];
        float4 v2 = reinterpret_cast<const float4*>(d_g2 + (size_t)r2 * F_OUT)[sub];
        float4 v3 = reinterpret_cast<const float4*>(d_g2 + (size_t)r3 * F_OUT)[sub];
        acc.x += v0.x + v1.x + v2.x + v3.x;
        acc.y += v0.y + v1.y + v2.y + v3.y;
        acc.z += v0.z + v1.z + v2.z + v3.z;
        acc.w += v0.w + v1.w + v2.w + v3.w;
    }
    for (; i < n; i++) {
        int r = d_csr[s + i];
        float4 v = reinterpret_cast<const float4*>(d_g2 + (size_t)r * F_OUT)[sub];
        acc.x += v.x; acc.y += v.y; acc.z += v.z; acc.w += v.w;
    }

    float sc = d_dinv[node];
    float4 b = reinterpret_cast<const float4*>(b2)[sub];
    float4 o;
    o.x = fmaf(acc.x, sc, b.x);
    o.y = fmaf(acc.y, sc, b.y);
    o.z = fmaf(acc.z, sc, b.z);
    o.w = fmaf(acc.w, sc, b.w);
    reinterpret_cast<float4*>(out + (size_t)node * F_OUT)[sub] = o;
}

// ---------------------------------------------------------------------------
// Launch.  Inputs: x, edge_index(int32), edge_weight, W1, b1, W2, b2
// ---------------------------------------------------------------------------
extern "C" void kernel_launch(void* const* d_in, const int* in_sizes, int n_in,
                              void* d_out, int out_size) {
    const float* x  = (const float*)d_in[0];
    const int*   ei = (const int*)d_in[1];
    const float* W1 = (const float*)d_in[3];
    const float* b1 = (const float*)d_in[4];
    const float* W2 = (const float*)d_in[5];
    const float* b2 = (const float*)d_in[6];
    float* out = (float*)d_out;

    init_kernel<<<(N_NODES + 255) / 256, 256>>>();
    count_deg_kernel<<<(N_EDGES + 255) / 256, 256>>>(ei);
    dinv_kernel<<<(N_NODES + 255) / 256, 256>>>();
    scan1_kernel<<<N_SCAN_BLKS, SCAN_BLK>>>();
    scan2_kernel<<<1, 256>>>();
    scan3_kernel<<<N_SCAN_BLKS, SCAN_BLK>>>();
    fill_csr_kernel<<<(N_EDGES + 255) / 256, 256>>>(ei);

    gemm1_kernel<<<(N_NODES + 63) / 64, 256>>>(x, W1);
    gather1_kernel<<<(N_NODES * 32 + 255) / 256, 256>>>(b1);
    gemm2_kernel<<<(N_NODES + 63) / 64, 256>>>(W2);
    gather2_kernel<<<(N_NODES * 16 + 255) / 256, 256>>>(b2, out);
}

// round 4
// speedup vs baseline: 2.1942x; 1.3767x over previous
#include <cuda_runtime.h>
#include <cuda_bf16.h>
#include <cstdint>

#define N_NODES 100000
#define N_EDGES 1600000
#define F_IN  128
#define F_MID 128
#define F_OUT 64

#define SCAN_BLK 512
#define N_SCAN_BLKS ((N_NODES + SCAN_BLK - 1) / SCAN_BLK)   // 196

// Scratch (static device globals; runtime allocation is forbidden)
__device__ __align__(16) int      d_deg_i[N_NODES];
__device__ __align__(16) int      d_fill [N_NODES];
__device__ __align__(16) int      d_ptr  [N_NODES];
__device__ __align__(16) int      d_bsum [N_SCAN_BLKS];
__device__ __align__(16) int      d_boff [N_SCAN_BLKS];
__device__ __align__(16) int      d_csr  [N_EDGES];
__device__ __align__(16) float    d_dinv [N_NODES];
__device__ __align__(16) float    d_g1   [(size_t)N_NODES * F_MID];
__device__ __align__(16) float    d_h    [(size_t)N_NODES * F_MID];
__device__ __align__(16) float    d_g2   [(size_t)N_NODES * F_OUT];
// W fragments in tf32, mma-fragment order: [kstep][ntile][lane][2]
__device__ __align__(16) uint32_t d_w1f  [16 * 16 * 32 * 2];   // 64KB
__device__ __align__(16) uint32_t d_w2f  [16 * 8  * 32 * 2];   // 32KB

// ---------------------------------------------------------------------------
// tf32 helpers
// ---------------------------------------------------------------------------
__device__ __forceinline__ uint32_t f2tf32(float f) {
    uint32_t r;
    asm("cvt.rna.tf32.f32 %0, %1;" : "=r"(r) : "f"(f));
    return r;
}

__device__ __forceinline__ void mma_tf32(float* c,
                                         uint32_t a0, uint32_t a1, uint32_t a2, uint32_t a3,
                                         uint32_t b0, uint32_t b1) {
    asm volatile("mma.sync.aligned.m16n8k8.row.col.f32.tf32.tf32.f32 "
                 "{%0,%1,%2,%3}, {%4,%5,%6,%7}, {%8,%9}, {%0,%1,%2,%3};"
                 : "+f"(c[0]), "+f"(c[1]), "+f"(c[2]), "+f"(c[3])
                 : "r"(a0), "r"(a1), "r"(a2), "r"(a3), "r"(b0), "r"(b1));
}

// ---------------------------------------------------------------------------
// Degree / CSR build.  edge_index is int32 on device (JAX x64-disabled).
// ---------------------------------------------------------------------------
__global__ void init_kernel() {
    int i = blockIdx.x * blockDim.x + threadIdx.x;
    if (i < N_NODES) { d_deg_i[i] = 0; d_fill[i] = 0; }
}

__global__ void count_deg_kernel(const int* __restrict__ ei) {
    int e = blockIdx.x * blockDim.x + threadIdx.x;
    if (e < N_EDGES) atomicAdd(&d_deg_i[ei[N_EDGES + e]], 1);
}

__global__ void dinv_kernel() {
    int i = blockIdx.x * blockDim.x + threadIdx.x;
    if (i < N_NODES) d_dinv[i] = rsqrtf((float)(1 + d_deg_i[i]));  // +1 self loop
}

__global__ void scan1_kernel() {
    __shared__ int sm[SCAN_BLK];
    int tid = threadIdx.x;
    int i = blockIdx.x * SCAN_BLK + tid;
    int v = (i < N_NODES) ? d_deg_i[i] : 0;
    sm[tid] = v;
    __syncthreads();
    #pragma unroll
    for (int off = 1; off < SCAN_BLK; off <<= 1) {
        int t = (tid >= off) ? sm[tid - off] : 0;
        __syncthreads();
        if (tid >= off) sm[tid] += t;
        __syncthreads();
    }
    if (i < N_NODES) d_ptr[i] = sm[tid] - v;       // exclusive
    if (tid == SCAN_BLK - 1) d_bsum[blockIdx.x] = sm[tid];
}

__global__ void scan2_kernel() {
    __shared__ int sm[256];
    int tid = threadIdx.x;
    int v = (tid < N_SCAN_BLKS) ? d_bsum[tid] : 0;
    sm[tid] = v;
    __syncthreads();
    #pragma unroll
    for (int off = 1; off < 256; off <<= 1) {
        int t = (tid >= off) ? sm[tid - off] : 0;
        __syncthreads();
        if (tid >= off) sm[tid] += t;
        __syncthreads();
    }
    if (tid < N_SCAN_BLKS) d_boff[tid] = sm[tid] - v;  // exclusive
}

__global__ void scan3_kernel() {
    int i = blockIdx.x * SCAN_BLK + threadIdx.x;
    if (i < N_NODES) d_ptr[i] += d_boff[blockIdx.x];
}

__global__ void fill_csr_kernel(const int* __restrict__ ei) {
    int e = blockIdx.x * blockDim.x + threadIdx.x;
    if (e < N_EDGES) {
        int r = ei[e];
        int c = ei[N_EDGES + e];
        int slot = atomicAdd(&d_fill[c], 1);
        d_csr[d_ptr[c] + slot] = r;
    }
}

// ---------------------------------------------------------------------------
// W fragment prep: tf32-convert and lay out in mma B-fragment order.
// B frag for m16n8k8 tf32 (col layout): b0 = B[t][g], b1 = B[t+4][g]
// with g = lane>>2, t = lane&3; B = W[k0 .. k0+8][n0 .. n0+8].
// ---------------------------------------------------------------------------
__global__ void w1f_prep_kernel(const float* __restrict__ W1) {
    int i = blockIdx.x * blockDim.x + threadIdx.x;
    if (i >= 16 * 16 * 32) return;
    int lane = i & 31, nt = (i >> 5) & 15, ks = i >> 9;
    int g = lane >> 2, t = lane & 3;
    d_w1f[2 * i]     = f2tf32(W1[(ks * 8 + t)     * F_MID + nt * 8 + g]);
    d_w1f[2 * i + 1] = f2tf32(W1[(ks * 8 + t + 4) * F_MID + nt * 8 + g]);
}

__global__ void w2f_prep_kernel(const float* __restrict__ W2) {
    int i = blockIdx.x * blockDim.x + threadIdx.x;
    if (i >= 16 * 8 * 32) return;
    int lane = i & 31, nt = (i >> 5) & 7, ks = i >> 8;
    int g = lane >> 2, t = lane & 3;
    d_w2f[2 * i]     = f2tf32(W2[(ks * 8 + t)     * F_OUT + nt * 8 + g]);
    d_w2f[2 * i + 1] = f2tf32(W2[(ks * 8 + t + 4) * F_OUT + nt * 8 + g]);
}

// ---------------------------------------------------------------------------
// GEMM1 (tensor core): g1[i][:] = (x[i][:] @ W1) * dinv[i]
// Warp computes 16 rows x 128 cols via m16n8k8 tf32 mma. 6250 warps exactly.
// ---------------------------------------------------------------------------
__global__ void __launch_bounds__(256) gemm1_tc(const float* __restrict__ x) {
    int wid = threadIdx.x >> 5, lane = threadIdx.x & 31;
    int wg = blockIdx.x * 8 + wid;
    if (wg >= N_NODES / 16) return;
    int rb = wg * 16;
    int g = lane >> 2, t = lane & 3;
    const float* arow0 = x + (size_t)(rb + g) * F_IN;
    const float* arow8 = x + (size_t)(rb + g + 8) * F_IN;

    float c[16][4] = {};
    const uint2* Bf = reinterpret_cast<const uint2*>(d_w1f);

    #pragma unroll 4
    for (int ks = 0; ks < 16; ks++) {
        int k0 = ks * 8;
        uint32_t a0 = f2tf32(arow0[k0 + t]);
        uint32_t a1 = f2tf32(arow8[k0 + t]);
        uint32_t a2 = f2tf32(arow0[k0 + t + 4]);
        uint32_t a3 = f2tf32(arow8[k0 + t + 4]);
        #pragma unroll
        for (int nt = 0; nt < 16; nt++) {
            uint2 b = Bf[(ks * 16 + nt) * 32 + lane];
            mma_tf32(c[nt], a0, a1, a2, a3, b.x, b.y);
        }
    }

    float s0 = d_dinv[rb + g], s8 = d_dinv[rb + g + 8];
    float* o0 = d_g1 + (size_t)(rb + g) * F_MID;
    float* o8 = d_g1 + (size_t)(rb + g + 8) * F_MID;
    #pragma unroll
    for (int nt = 0; nt < 16; nt++) {
        int col = nt * 8 + 2 * t;
        *reinterpret_cast<float2*>(o0 + col) = make_float2(c[nt][0] * s0, c[nt][1] * s0);
        *reinterpret_cast<float2*>(o8 + col) = make_float2(c[nt][2] * s8, c[nt][3] * s8);
    }
}

// ---------------------------------------------------------------------------
// GEMM2 (tensor core): g2[i][:] = (h[i][:] @ W2) * dinv[i]   (N = 64)
// ---------------------------------------------------------------------------
__global__ void __launch_bounds__(256) gemm2_tc() {
    int wid = threadIdx.x >> 5, lane = threadIdx.x & 31;
    int wg = blockIdx.x * 8 + wid;
    if (wg >= N_NODES / 16) return;
    int rb = wg * 16;
    int g = lane >> 2, t = lane & 3;
    const float* arow0 = d_h + (size_t)(rb + g) * F_MID;
    const float* arow8 = d_h + (size_t)(rb + g + 8) * F_MID;

    float c[8][4] = {};
    const uint2* Bf = reinterpret_cast<const uint2*>(d_w2f);

    #pragma unroll 4
    for (int ks = 0; ks < 16; ks++) {
        int k0 = ks * 8;
        uint32_t a0 = f2tf32(arow0[k0 + t]);
        uint32_t a1 = f2tf32(arow8[k0 + t]);
        uint32_t a2 = f2tf32(arow0[k0 + t + 4]);
        uint32_t a3 = f2tf32(arow8[k0 + t + 4]);
        #pragma unroll
        for (int nt = 0; nt < 8; nt++) {
            uint2 b = Bf[(ks * 8 + nt) * 32 + lane];
            mma_tf32(c[nt], a0, a1, a2, a3, b.x, b.y);
        }
    }

    float s0 = d_dinv[rb + g], s8 = d_dinv[rb + g + 8];
    float* o0 = d_g2 + (size_t)(rb + g) * F_OUT;
    float* o8 = d_g2 + (size_t)(rb + g + 8) * F_OUT;
    #pragma unroll
    for (int nt = 0; nt < 8; nt++) {
        int col = nt * 8 + 2 * t;
        *reinterpret_cast<float2*>(o0 + col) = make_float2(c[nt][0] * s0, c[nt][1] * s0);
        *reinterpret_cast<float2*>(o8 + col) = make_float2(c[nt][2] * s8, c[nt][3] * s8);
    }
}

// ---------------------------------------------------------------------------
// Gather layer 1: warp per node.  h[c] = relu(dinv[c]*(g1[c] + sum_in g1[r]) + b1)
// ---------------------------------------------------------------------------
__global__ void __launch_bounds__(256) gather1_kernel(const float* __restrict__ b1) {
    int node = (blockIdx.x * blockDim.x + threadIdx.x) >> 5;
    int lane = threadIdx.x & 31;
    if (node >= N_NODES) return;
    int s = d_ptr[node];
    int n = d_deg_i[node];

    float4 acc = reinterpret_cast<const float4*>(d_g1 + (size_t)node * F_MID)[lane];
    int i = 0;
    for (; i + 4 <= n; i += 4) {
        int r0 = d_csr[s + i], r1 = d_csr[s + i + 1];
        int r2 = d_csr[s + i + 2], r3 = d_csr[s + i + 3];
        float4 v0 = reinterpret_cast<const float4*>(d_g1 + (size_t)r0 * F_MID)[lane];
        float4 v1 = reinterpret_cast<const float4*>(d_g1 + (size_t)r1 * F_MID)[lane];
        float4 v2 = reinterpret_cast<const float4*>(d_g1 + (size_t)r2 * F_MID)[lane];
        float4 v3 = reinterpret_cast<const float4*>(d_g1 + (size_t)r3 * F_MID)[lane];
        acc.x += v0.x + v1.x + v2.x + v3.x;
        acc.y += v0.y + v1.y + v2.y + v3.y;
        acc.z += v0.z + v1.z + v2.z + v3.z;
        acc.w += v0.w + v1.w + v2.w + v3.w;
    }
    for (; i < n; i++) {
        int r = d_csr[s + i];
        float4 v = reinterpret_cast<const float4*>(d_g1 + (size_t)r * F_MID)[lane];
        acc.x += v.x; acc.y += v.y; acc.z += v.z; acc.w += v.w;
    }

    float sc = d_dinv[node];
    float4 b = reinterpret_cast<const float4*>(b1)[lane];
    float4 o;
    o.x = fmaxf(fmaf(acc.x, sc, b.x), 0.0f);
    o.y = fmaxf(fmaf(acc.y, sc, b.y), 0.0f);
    o.z = fmaxf(fmaf(acc.z, sc, b.z), 0.0f);
    o.w = fmaxf(fmaf(acc.w, sc, b.w), 0.0f);
    reinterpret_cast<float4*>(d_h + (size_t)node * F_MID)[lane] = o;
}

// ---------------------------------------------------------------------------
// Gather layer 2: half-warp per node.  out[c] = dinv[c]*(g2[c] + sum_in g2[r]) + b2
// ---------------------------------------------------------------------------
__global__ void __launch_bounds__(256) gather2_kernel(const float* __restrict__ b2,
                                                      float* __restrict__ out) {
    int t = blockIdx.x * blockDim.x + threadIdx.x;
    int node = t >> 4;
    int sub = t & 15;
    if (node >= N_NODES) return;
    int s = d_ptr[node];
    int n = d_deg_i[node];

    float4 acc = reinterpret_cast<const float4*>(d_g2 + (size_t)node * F_OUT)[sub];
    int i = 0;
    for (; i + 4 <= n; i += 4) {
        int r0 = d_csr[s + i], r1 = d_csr[s + i + 1];
        int r2 = d_csr[s + i + 2], r3 = d_csr[s + i + 3];
        float4 v0 = reinterpret_cast<const float4*>(d_g2 + (size_t)r0 * F_OUT)[sub];
        float4 v1 = reinterpret_cast<const float4*>(d_g2 + (size_t)r1 * F_OUT)[sub];
        float4 v2 = reinterpret_cast<const float4*>(d_g2 + (size_t)r2 * F_OUT)[sub];
        float4 v3 = reinterpret_cast<const float4*>(d_g2 + (size_t)r3 * F_OUT)[sub];
        acc.x += v0.x + v1.x + v2.x + v3.x;
        acc.y += v0.y + v1.y + v2.y + v3.y;
        acc.z += v0.z + v1.z + v2.z + v3.z;
        acc.w += v0.w + v1.w + v2.w + v3.w;
    }
    for (; i < n; i++) {
        int r = d_csr[s + i];
        float4 v = reinterpret_cast<const float4*>(d_g2 + (size_t)r * F_OUT)[sub];
        acc.x += v.x; acc.y += v.y; acc.z += v.z; acc.w += v.w;
    }

    float sc = d_dinv[node];
    float4 b = reinterpret_cast<const float4*>(b2)[sub];
    float4 o;
    o.x = fmaf(acc.x, sc, b.x);
    o.y = fmaf(acc.y, sc, b.y);
    o.z = fmaf(acc.z, sc, b.z);
    o.w = fmaf(acc.w, sc, b.w);
    reinterpret_cast<float4*>(out + (size_t)node * F_OUT)[sub] = o;
}

// ---------------------------------------------------------------------------
// Launch.  Inputs: x, edge_index(int32), edge_weight, W1, b1, W2, b2
// ---------------------------------------------------------------------------
extern "C" void kernel_launch(void* const* d_in, const int* in_sizes, int n_in,
                              void* d_out, int out_size) {
    const float* x  = (const float*)d_in[0];
    const int*   ei = (const int*)d_in[1];
    const float* W1 = (const float*)d_in[3];
    const float* b1 = (const float*)d_in[4];
    const float* W2 = (const float*)d_in[5];
    const float* b2 = (const float*)d_in[6];
    float* out = (float*)d_out;

    const int nwarp_blocks = (N_NODES / 16 + 7) / 8;   // 782

    init_kernel<<<(N_NODES + 255) / 256, 256>>>();
    count_deg_kernel<<<(N_EDGES + 255) / 256, 256>>>(ei);
    w1f_prep_kernel<<<(16 * 16 * 32 + 255) / 256, 256>>>(W1);
    w2f_prep_kernel<<<(16 * 8 * 32 + 255) / 256, 256>>>(W2);
    dinv_kernel<<<(N_NODES + 255) / 256, 256>>>();
    scan1_kernel<<<N_SCAN_BLKS, SCAN_BLK>>>();
    scan2_kernel<<<1, 256>>>();
    scan3_kernel<<<N_SCAN_BLKS, SCAN_BLK>>>();
    fill_csr_kernel<<<(N_EDGES + 255) / 256, 256>>>(ei);

    gemm1_tc<<<nwarp_blocks, 256>>>(x);
    gather1_kernel<<<(N_NODES * 32 + 255) / 256, 256>>>(b1);
    gemm2_tc<<<nwarp_blocks, 256>>>();
    gather2_kernel<<<(N_NODES * 16 + 255) / 256, 256>>>(b2, out);
}

// round 6
// speedup vs baseline: 2.5588x; 1.1661x over previous
#include <cuda_runtime.h>
#include <cuda_fp16.h>
#include <cstdint>

#define N_NODES 100000
#define N_EDGES 1600000
#define F_IN  128
#define F_MID 128
#define F_OUT 64

#define SCAN_BLK 512
#define N_SCAN_BLKS ((N_NODES + SCAN_BLK - 1) / SCAN_BLK)   // 196

// Scratch (static device globals; runtime allocation is forbidden)
__device__ __align__(16) int      d_deg_i[N_NODES];
__device__ __align__(16) int      d_fill [N_NODES];
__device__ __align__(16) int      d_ptr  [N_NODES];
__device__ __align__(16) int      d_bsum [N_SCAN_BLKS];
__device__ __align__(16) int      d_boff [N_SCAN_BLKS];
__device__ __align__(16) int      d_csr  [N_EDGES];
__device__ __align__(16) float    d_dinv [N_NODES];
__device__ __align__(16) __half   d_g1   [(size_t)N_NODES * F_MID];  // fp16
__device__ __align__(16) __half   d_h    [(size_t)N_NODES * F_MID];  // fp16
__device__ __align__(16) __half   d_g2   [(size_t)N_NODES * F_OUT];  // fp16
// W fragments in tf32, mma-fragment order: [kstep][ntile][lane][2]
__device__ __align__(16) uint32_t d_w1f  [16 * 16 * 32 * 2];   // 64KB
__device__ __align__(16) uint32_t d_w2f  [16 * 8  * 32 * 2];   // 32KB

// ---------------------------------------------------------------------------
// tf32 helpers
// ---------------------------------------------------------------------------
__device__ __forceinline__ uint32_t f2tf32(float f) {
    uint32_t r;
    asm("cvt.rna.tf32.f32 %0, %1;" : "=r"(r) : "f"(f));
    return r;
}

__device__ __forceinline__ void mma_tf32(float* c,
                                         uint32_t a0, uint32_t a1, uint32_t a2, uint32_t a3,
                                         uint32_t b0, uint32_t b1) {
    asm volatile("mma.sync.aligned.m16n8k8.row.col.f32.tf32.tf32.f32 "
                 "{%0,%1,%2,%3}, {%4,%5,%6,%7}, {%8,%9}, {%0,%1,%2,%3};"
                 : "+f"(c[0]), "+f"(c[1]), "+f"(c[2]), "+f"(c[3])
                 : "r"(a0), "r"(a1), "r"(a2), "r"(a3), "r"(b0), "r"(b1));
}

// Accumulate 8 halves (uint4) into 8 fp32 accumulators
__device__ __forceinline__ void acc8(float* acc, uint4 v) {
    const __half2* hp = reinterpret_cast<const __half2*>(&v);
    #pragma unroll
    for (int j = 0; j < 4; j++) {
        float2 f = __half22float2(hp[j]);
        acc[2 * j]     += f.x;
        acc[2 * j + 1] += f.y;
    }
}

// ---------------------------------------------------------------------------
// Degree / CSR build.  edge_index is int32 on device (JAX x64-disabled).
// ---------------------------------------------------------------------------
__global__ void init_kernel() {
    int i = blockIdx.x * blockDim.x + threadIdx.x;
    if (i < N_NODES) { d_deg_i[i] = 0; d_fill[i] = 0; }
}

__global__ void count_deg_kernel(const int* __restrict__ ei) {
    int e = blockIdx.x * blockDim.x + threadIdx.x;
    if (e < N_EDGES) atomicAdd(&d_deg_i[ei[N_EDGES + e]], 1);
}

// scan1 also computes dinv (deg ready after count)
__global__ void scan1_kernel() {
    __shared__ int sm[SCAN_BLK];
    int tid = threadIdx.x;
    int i = blockIdx.x * SCAN_BLK + tid;
    int v = (i < N_NODES) ? d_deg_i[i] : 0;
    if (i < N_NODES) d_dinv[i] = rsqrtf((float)(1 + v));
    sm[tid] = v;
    __syncthreads();
    #pragma unroll
    for (int off = 1; off < SCAN_BLK; off <<= 1) {
        int t = (tid >= off) ? sm[tid - off] : 0;
        __syncthreads();
        if (tid >= off) sm[tid] += t;
        __syncthreads();
    }
    if (i < N_NODES) d_ptr[i] = sm[tid] - v;       // exclusive
    if (tid == SCAN_BLK - 1) d_bsum[blockIdx.x] = sm[tid];
}

__global__ void scan2_kernel() {
    __shared__ int sm[256];
    int tid = threadIdx.x;
    int v = (tid < N_SCAN_BLKS) ? d_bsum[tid] : 0;
    sm[tid] = v;
    __syncthreads();
    #pragma unroll
    for (int off = 1; off < 256; off <<= 1) {
        int t = (tid >= off) ? sm[tid - off] : 0;
        __syncthreads();
        if (tid >= off) sm[tid] += t;
        __syncthreads();
    }
    if (tid < N_SCAN_BLKS) d_boff[tid] = sm[tid] - v;  // exclusive
}

__global__ void scan3_kernel() {
    int i = blockIdx.x * SCAN_BLK + threadIdx.x;
    if (i < N_NODES) d_ptr[i] += d_boff[blockIdx.x];
}

__global__ void fill_csr_kernel(const int* __restrict__ ei) {
    int e = blockIdx.x * blockDim.x + threadIdx.x;
    if (e < N_EDGES) {
        int r = ei[e];
        int c = ei[N_EDGES + e];
        int slot = atomicAdd(&d_fill[c], 1);
        d_csr[d_ptr[c] + slot] = r;
    }
}

// ---------------------------------------------------------------------------
// W fragment prep (both weights in one kernel): tf32, mma B-fragment order.
// b0 = B[t][g], b1 = B[t+4][g], g = lane>>2, t = lane&3.
// ---------------------------------------------------------------------------
__global__ void wf_prep_kernel(const float* __restrict__ W1,
                               const float* __restrict__ W2) {
    int i = blockIdx.x * blockDim.x + threadIdx.x;
    if (i < 16 * 16 * 32) {
        int lane = i & 31, nt = (i >> 5) & 15, ks = i >> 9;
        int g = lane >> 2, t = lane & 3;
        d_w1f[2 * i]     = f2tf32(W1[(ks * 8 + t)     * F_MID + nt * 8 + g]);
        d_w1f[2 * i + 1] = f2tf32(W1[(ks * 8 + t + 4) * F_MID + nt * 8 + g]);
    } else if (i < 16 * 16 * 32 + 16 * 8 * 32) {
        int j = i - 16 * 16 * 32;
        int lane = j & 31, nt = (j >> 5) & 7, ks = j >> 8;
        int g = lane >> 2, t = lane & 3;
        d_w2f[2 * j]     = f2tf32(W2[(ks * 8 + t)     * F_OUT + nt * 8 + g]);
        d_w2f[2 * j + 1] = f2tf32(W2[(ks * 8 + t + 4) * F_OUT + nt * 8 + g]);
    }
}

// ---------------------------------------------------------------------------
// GEMM1 (tensor core): g1[i][:] = fp16((x[i][:] @ W1) * dinv[i])
// Warp computes 16 rows x 128 cols via m16n8k8 tf32 mma. 6250 warps exactly.
// ---------------------------------------------------------------------------
__global__ void __launch_bounds__(256) gemm1_tc(const float* __restrict__ x) {
    int wid = threadIdx.x >> 5, lane = threadIdx.x & 31;
    int wg = blockIdx.x * 8 + wid;
    if (wg >= N_NODES / 16) return;
    int rb = wg * 16;
    int g = lane >> 2, t = lane & 3;
    const float* arow0 = x + (size_t)(rb + g) * F_IN;
    const float* arow8 = x + (size_t)(rb + g + 8) * F_IN;

    float c[16][4] = {};
    const uint2* Bf = reinterpret_cast<const uint2*>(d_w1f);

    #pragma unroll 4
    for (int ks = 0; ks < 16; ks++) {
        int k0 = ks * 8;
        uint32_t a0 = f2tf32(arow0[k0 + t]);
        uint32_t a1 = f2tf32(arow8[k0 + t]);
        uint32_t a2 = f2tf32(arow0[k0 + t + 4]);
        uint32_t a3 = f2tf32(arow8[k0 + t + 4]);
        #pragma unroll
        for (int nt = 0; nt < 16; nt++) {
            uint2 b = Bf[(ks * 16 + nt) * 32 + lane];
            mma_tf32(c[nt], a0, a1, a2, a3, b.x, b.y);
        }
    }

    float s0 = d_dinv[rb + g], s8 = d_dinv[rb + g + 8];
    __half2* o0 = reinterpret_cast<__half2*>(d_g1 + (size_t)(rb + g) * F_MID);
    __half2* o8 = reinterpret_cast<__half2*>(d_g1 + (size_t)(rb + g + 8) * F_MID);
    #pragma unroll
    for (int nt = 0; nt < 16; nt++) {
        int c2 = (nt * 8 + 2 * t) >> 1;
        o0[c2] = __floats2half2_rn(c[nt][0] * s0, c[nt][1] * s0);
        o8[c2] = __floats2half2_rn(c[nt][2] * s8, c[nt][3] * s8);
    }
}

// ---------------------------------------------------------------------------
// Gather layer 1: 16 threads per node (128 halves = 16 x uint4).
// h[c] = fp16(relu(dinv[c]*(g1[c] + sum_in g1[r]) + b1))
// ---------------------------------------------------------------------------
__global__ void __launch_bounds__(256) gather1_kernel(const float* __restrict__ b1) {
    int tt = blockIdx.x * blockDim.x + threadIdx.x;
    int node = tt >> 4;
    int sub  = tt & 15;
    if (node >= N_NODES) return;
    int s = d_ptr[node];
    int n = d_deg_i[node];

    float acc[8] = {};
    acc8(acc, reinterpret_cast<const uint4*>(d_g1 + (size_t)node * F_MID)[sub]);

    int i = 0;
    for (; i + 4 <= n; i += 4) {
        int r0 = d_csr[s + i], r1 = d_csr[s + i + 1];
        int r2 = d_csr[s + i + 2], r3 = d_csr[s + i + 3];
        uint4 v0 = reinterpret_cast<const uint4*>(d_g1 + (size_t)r0 * F_MID)[sub];
        uint4 v1 = reinterpret_cast<const uint4*>(d_g1 + (size_t)r1 * F_MID)[sub];
        uint4 v2 = reinterpret_cast<const uint4*>(d_g1 + (size_t)r2 * F_MID)[sub];
        uint4 v3 = reinterpret_cast<const uint4*>(d_g1 + (size_t)r3 * F_MID)[sub];
        acc8(acc, v0); acc8(acc, v1); acc8(acc, v2); acc8(acc, v3);
    }
    for (; i < n; i++) {
        int r = d_csr[s + i];
        acc8(acc, reinterpret_cast<const uint4*>(d_g1 + (size_t)r * F_MID)[sub]);
    }

    float sc = d_dinv[node];
    float4 blo = reinterpret_cast<const float4*>(b1)[sub * 2];
    float4 bhi = reinterpret_cast<const float4*>(b1)[sub * 2 + 1];
    float o[8];
    o[0] = fmaxf(fmaf(acc[0], sc, blo.x), 0.0f);
    o[1] = fmaxf(fmaf(acc[1], sc, blo.y), 0.0f);
    o[2] = fmaxf(fmaf(acc[2], sc, blo.z), 0.0f);
    o[3] = fmaxf(fmaf(acc[3], sc, blo.w), 0.0f);
    o[4] = fmaxf(fmaf(acc[4], sc, bhi.x), 0.0f);
    o[5] = fmaxf(fmaf(acc[5], sc, bhi.y), 0.0f);
    o[6] = fmaxf(fmaf(acc[6], sc, bhi.z), 0.0f);
    o[7] = fmaxf(fmaf(acc[7], sc, bhi.w), 0.0f);

    uint4 ov;
    __half2* op = reinterpret_cast<__half2*>(&ov);
    op[0] = __floats2half2_rn(o[0], o[1]);
    op[1] = __floats2half2_rn(o[2], o[3]);
    op[2] = __floats2half2_rn(o[4], o[5]);
    op[3] = __floats2half2_rn(o[6], o[7]);
    reinterpret_cast<uint4*>(d_h + (size_t)node * F_MID)[sub] = ov;
}

// ---------------------------------------------------------------------------
// GEMM2 (tensor core): g2[i][:] = fp16((h[i][:] @ W2) * dinv[i])   (N = 64)
// ---------------------------------------------------------------------------
__global__ void __launch_bounds__(256) gemm2_tc() {
    int wid = threadIdx.x >> 5, lane = threadIdx.x & 31;
    int wg = blockIdx.x * 8 + wid;
    if (wg >= N_NODES / 16) return;
    int rb = wg * 16;
    int g = lane >> 2, t = lane & 3;
    const __half* arow0 = d_h + (size_t)(rb + g) * F_MID;
    const __half* arow8 = d_h + (size_t)(rb + g + 8) * F_MID;

    float c[8][4] = {};
    const uint2* Bf = reinterpret_cast<const uint2*>(d_w2f);

    #pragma unroll 4
    for (int ks = 0; ks < 16; ks++) {
        int k0 = ks * 8;
        uint32_t a0 = f2tf32(__half2float(arow0[k0 + t]));
        uint32_t a1 = f2tf32(__half2float(arow8[k0 + t]));
        uint32_t a2 = f2tf32(__half2float(arow0[k0 + t + 4]));
        uint32_t a3 = f2tf32(__half2float(arow8[k0 + t + 4]));
        #pragma unroll
        for (int nt = 0; nt < 8; nt++) {
            uint2 b = Bf[(ks * 8 + nt) * 32 + lane];
            mma_tf32(c[nt], a0, a1, a2, a3, b.x, b.y);
        }
    }

    float s0 = d_dinv[rb + g], s8 = d_dinv[rb + g + 8];
    __half2* o0 = reinterpret_cast<__half2*>(d_g2 + (size_t)(rb + g) * F_OUT);
    __half2* o8 = reinterpret_cast<__half2*>(d_g2 + (size_t)(rb + g + 8) * F_OUT);
    #pragma unroll
    for (int nt = 0; nt < 8; nt++) {
        int c2 = (nt * 8 + 2 * t) >> 1;
        o0[c2] = __floats2half2_rn(c[nt][0] * s0, c[nt][1] * s0);
        o8[c2] = __floats2half2_rn(c[nt][2] * s8, c[nt][3] * s8);
    }
}

// ---------------------------------------------------------------------------
// Gather layer 2: 8 threads per node (64 halves = 8 x uint4).
// out[c] = dinv[c]*(g2[c] + sum_in g2[r]) + b2   (fp32 output)
// ---------------------------------------------------------------------------
__global__ void __launch_bounds__(256) gather2_kernel(const float* __restrict__ b2,
                                                      float* __restrict__ out) {
    int tt = blockIdx.x * blockDim.x + threadIdx.x;
    int node = tt >> 3;
    int sub  = tt & 7;
    if (node >= N_NODES) return;
    int s = d_ptr[node];
    int n = d_deg_i[node];

    float acc[8] = {};
    acc8(acc, reinterpret_cast<const uint4*>(d_g2 + (size_t)node * F_OUT)[sub]);

    int i = 0;
    for (; i + 4 <= n; i += 4) {
        int r0 = d_csr[s + i], r1 = d_csr[s + i + 1];
        int r2 = d_csr[s + i + 2], r3 = d_csr[s + i + 3];
        uint4 v0 = reinterpret_cast<const uint4*>(d_g2 + (size_t)r0 * F_OUT)[sub];
        uint4 v1 = reinterpret_cast<const uint4*>(d_g2 + (size_t)r1 * F_OUT)[sub];
        uint4 v2 = reinterpret_cast<const uint4*>(d_g2 + (size_t)r2 * F_OUT)[sub];
        uint4 v3 = reinterpret_cast<const uint4*>(d_g2 + (size_t)r3 * F_OUT)[sub];
        acc8(acc, v0); acc8(acc, v1); acc8(acc, v2); acc8(acc, v3);
    }
    for (; i < n; i++) {
        int r = d_csr[s + i];
        acc8(acc, reinterpret_cast<const uint4*>(d_g2 + (size_t)r * F_OUT)[sub]);
    }

    float sc = d_dinv[node];
    float4 blo = reinterpret_cast<const float4*>(b2)[sub * 2];
    float4 bhi = reinterpret_cast<const float4*>(b2)[sub * 2 + 1];
    float4 olo, ohi;
    olo.x = fmaf(acc[0], sc, blo.x);
    olo.y = fmaf(acc[1], sc, blo.y);
    olo.z = fmaf(acc[2], sc, blo.z);
    olo.w = fmaf(acc[3], sc, blo.w);
    ohi.x = fmaf(acc[4], sc, bhi.x);
    ohi.y = fmaf(acc[5], sc, bhi.y);
    ohi.z = fmaf(acc[6], sc, bhi.z);
    ohi.w = fmaf(acc[7], sc, bhi.w);
    float4* orow = reinterpret_cast<float4*>(out + (size_t)node * F_OUT);
    orow[sub * 2]     = olo;
    orow[sub * 2 + 1] = ohi;
}

// ---------------------------------------------------------------------------
// Launch.  Inputs: x, edge_index(int32), edge_weight, W1, b1, W2, b2
// ---------------------------------------------------------------------------
extern "C" void kernel_launch(void* const* d_in, const int* in_sizes, int n_in,
                              void* d_out, int out_size) {
    const float* x  = (const float*)d_in[0];
    const int*   ei = (const int*)d_in[1];
    const float* W1 = (const float*)d_in[3];
    const float* b1 = (const float*)d_in[4];
    const float* W2 = (const float*)d_in[5];
    const float* b2 = (const float*)d_in[6];
    float* out = (float*)d_out;

    const int nwarp_blocks = (N_NODES / 16 + 7) / 8;   // 782

    init_kernel<<<(N_NODES + 255) / 256, 256>>>();
    count_deg_kernel<<<(N_EDGES + 255) / 256, 256>>>(ei);
    wf_prep_kernel<<<(16 * 16 * 32 + 16 * 8 * 32 + 255) / 256, 256>>>(W1, W2);
    scan1_kernel<<<N_SCAN_BLKS, SCAN_BLK>>>();
    scan2_kernel<<<1, 256>>>();
    scan3_kernel<<<N_SCAN_BLKS, SCAN_BLK>>>();
    fill_csr_kernel<<<(N_EDGES + 255) / 256, 256>>>(ei);

    gemm1_tc<<<nwarp_blocks, 256>>>(x);
    gather1_kernel<<<(N_NODES * 16 + 255) / 256, 256>>>(b1);
    gemm2_tc<<<nwarp_blocks, 256>>>();
    gather2_kernel<<<(N_NODES * 8 + 255) / 256, 256>>>(b2, out);
}

// round 7
// speedup vs baseline: 2.7191x; 1.0626x over previous
#include <cuda_runtime.h>
#include <cuda_fp16.h>
#include <cstdint>

#define N_NODES 100000
#define N_EDGES 1600000
#define F_IN  128
#define F_MID 128
#define F_OUT 64

#define SCAN_BLK 512
#define N_SCAN_BLKS ((N_NODES + SCAN_BLK - 1) / SCAN_BLK)   // 196

// Scratch (static device globals; runtime allocation is forbidden)
__device__ __align__(16) int      d_deg_i[N_NODES];
__device__ __align__(16) int      d_fill [N_NODES];
__device__ __align__(16) int      d_ptr  [N_NODES];
__device__ __align__(16) int      d_bsum [N_SCAN_BLKS];
__device__ __align__(16) int      d_boff [N_SCAN_BLKS];
__device__ __align__(16) int      d_csr  [N_EDGES];
__device__ __align__(16) float    d_dinv [N_NODES];
__device__ __align__(16) __half   d_g1   [(size_t)N_NODES * F_MID];
__device__ __align__(16) __half   d_h    [(size_t)N_NODES * F_MID];
__device__ __align__(16) __half   d_g2   [(size_t)N_NODES * F_OUT];
// W fragments in tf32, mma-fragment order: [kstep][ntile][lane][2]
__device__ __align__(16) uint32_t d_w1f  [16 * 16 * 32 * 2];   // 64KB
__device__ __align__(16) uint32_t d_w2f  [16 * 8  * 32 * 2];   // 32KB

// ---------------------------------------------------------------------------
// tf32 helpers
// ---------------------------------------------------------------------------
__device__ __forceinline__ uint32_t f2tf32(float f) {
    uint32_t r;
    asm("cvt.rna.tf32.f32 %0, %1;" : "=r"(r) : "f"(f));
    return r;
}

__device__ __forceinline__ void mma_tf32(float* c,
                                         uint32_t a0, uint32_t a1, uint32_t a2, uint32_t a3,
                                         uint32_t b0, uint32_t b1) {
    asm volatile("mma.sync.aligned.m16n8k8.row.col.f32.tf32.tf32.f32 "
                 "{%0,%1,%2,%3}, {%4,%5,%6,%7}, {%8,%9}, {%0,%1,%2,%3};"
                 : "+f"(c[0]), "+f"(c[1]), "+f"(c[2]), "+f"(c[3])
                 : "r"(a0), "r"(a1), "r"(a2), "r"(a3), "r"(b0), "r"(b1));
}

// Accumulate 8 halves (uint4) into 8 fp32 accumulators
__device__ __forceinline__ void acc8(float* acc, uint4 v) {
    const __half2* hp = reinterpret_cast<const __half2*>(&v);
    #pragma unroll
    for (int j = 0; j < 4; j++) {
        float2 f = __half22float2(hp[j]);
        acc[2 * j]     += f.x;
        acc[2 * j + 1] += f.y;
    }
}

// ---------------------------------------------------------------------------
// Degree / CSR build.  edge_index is int32 on device (JAX x64-disabled).
// ---------------------------------------------------------------------------
__global__ void init_kernel() {
    int i = blockIdx.x * blockDim.x + threadIdx.x;
    if (i < N_NODES) { d_deg_i[i] = 0; d_fill[i] = 0; }
}

__global__ void count_deg_kernel(const int* __restrict__ ei) {
    int e = blockIdx.x * blockDim.x + threadIdx.x;
    if (e < N_EDGES) atomicAdd(&d_deg_i[ei[N_EDGES + e]], 1);
}

__global__ void dinv_kernel() {
    int i = blockIdx.x * blockDim.x + threadIdx.x;
    if (i < N_NODES) d_dinv[i] = rsqrtf((float)(1 + d_deg_i[i]));
}

__global__ void scan1_kernel() {
    __shared__ int sm[SCAN_BLK];
    int tid = threadIdx.x;
    int i = blockIdx.x * SCAN_BLK + tid;
    int v = (i < N_NODES) ? d_deg_i[i] : 0;
    sm[tid] = v;
    __syncthreads();
    #pragma unroll
    for (int off = 1; off < SCAN_BLK; off <<= 1) {
        int t = (tid >= off) ? sm[tid - off] : 0;
        __syncthreads();
        if (tid >= off) sm[tid] += t;
        __syncthreads();
    }
    if (i < N_NODES) d_ptr[i] = sm[tid] - v;       // exclusive
    if (tid == SCAN_BLK - 1) d_bsum[blockIdx.x] = sm[tid];
}

__global__ void scan2_kernel() {
    __shared__ int sm[256];
    int tid = threadIdx.x;
    int v = (tid < N_SCAN_BLKS) ? d_bsum[tid] : 0;
    sm[tid] = v;
    __syncthreads();
    #pragma unroll
    for (int off = 1; off < 256; off <<= 1) {
        int t = (tid >= off) ? sm[tid - off] : 0;
        __syncthreads();
        if (tid >= off) sm[tid] += t;
        __syncthreads();
    }
    if (tid < N_SCAN_BLKS) d_boff[tid] = sm[tid] - v;  // exclusive
}

__global__ void scan3_kernel() {
    int i = blockIdx.x * SCAN_BLK + threadIdx.x;
    if (i < N_NODES) d_ptr[i] += d_boff[blockIdx.x];
}

__global__ void fill_csr_kernel(const int* __restrict__ ei) {
    int e = blockIdx.x * blockDim.x + threadIdx.x;
    if (e < N_EDGES) {
        int r = ei[e];
        int c = ei[N_EDGES + e];
        int slot = atomicAdd(&d_fill[c], 1);
        d_csr[d_ptr[c] + slot] = r;
    }
}

// ---------------------------------------------------------------------------
// W fragment prep (both weights in one kernel): tf32, mma B-fragment order.
// ---------------------------------------------------------------------------
__global__ void wf_prep_kernel(const float* __restrict__ W1,
                               const float* __restrict__ W2) {
    int i = blockIdx.x * blockDim.x + threadIdx.x;
    if (i < 16 * 16 * 32) {
        int lane = i & 31, nt = (i >> 5) & 15, ks = i >> 9;
        int g = lane >> 2, t = lane & 3;
        d_w1f[2 * i]     = f2tf32(W1[(ks * 8 + t)     * F_MID + nt * 8 + g]);
        d_w1f[2 * i + 1] = f2tf32(W1[(ks * 8 + t + 4) * F_MID + nt * 8 + g]);
    } else if (i < 16 * 16 * 32 + 16 * 8 * 32) {
        int j = i - 16 * 16 * 32;
        int lane = j & 31, nt = (j >> 5) & 7, ks = j >> 8;
        int g = lane >> 2, t = lane & 3;
        d_w2f[2 * j]     = f2tf32(W2[(ks * 8 + t)     * F_OUT + nt * 8 + g]);
        d_w2f[2 * j + 1] = f2tf32(W2[(ks * 8 + t + 4) * F_OUT + nt * 8 + g]);
    }
}

// ---------------------------------------------------------------------------
// GEMM1 (tensor core): g1[i][:] = fp16((x[i][:] @ W1) * dinv[i])
// ---------------------------------------------------------------------------
__global__ void __launch_bounds__(256) gemm1_tc(const float* __restrict__ x) {
    int wid = threadIdx.x >> 5, lane = threadIdx.x & 31;
    int wg = blockIdx.x * 8 + wid;
    if (wg >= N_NODES / 16) return;
    int rb = wg * 16;
    int g = lane >> 2, t = lane & 3;
    const float* arow0 = x + (size_t)(rb + g) * F_IN;
    const float* arow8 = x + (size_t)(rb + g + 8) * F_IN;

    float c[16][4] = {};
    const uint2* Bf = reinterpret_cast<const uint2*>(d_w1f);

    #pragma unroll 4
    for (int ks = 0; ks < 16; ks++) {
        int k0 = ks * 8;
        uint32_t a0 = f2tf32(arow0[k0 + t]);
        uint32_t a1 = f2tf32(arow8[k0 + t]);
        uint32_t a2 = f2tf32(arow0[k0 + t + 4]);
        uint32_t a3 = f2tf32(arow8[k0 + t + 4]);
        #pragma unroll
        for (int nt = 0; nt < 16; nt++) {
            uint2 b = Bf[(ks * 16 + nt) * 32 + lane];
            mma_tf32(c[nt], a0, a1, a2, a3, b.x, b.y);
        }
    }

    float s0 = d_dinv[rb + g], s8 = d_dinv[rb + g + 8];
    __half2* o0 = reinterpret_cast<__half2*>(d_g1 + (size_t)(rb + g) * F_MID);
    __half2* o8 = reinterpret_cast<__half2*>(d_g1 + (size_t)(rb + g + 8) * F_MID);
    #pragma unroll
    for (int nt = 0; nt < 16; nt++) {
        int c2 = (nt * 8 + 2 * t) >> 1;
        o0[c2] = __floats2half2_rn(c[nt][0] * s0, c[nt][1] * s0);
        o8[c2] = __floats2half2_rn(c[nt][2] * s8, c[nt][3] * s8);
    }
}

// ---------------------------------------------------------------------------
// Gather layer 1: 16 threads per node (128 halves = 16 x uint4), unroll 8.
// ---------------------------------------------------------------------------
__global__ void __launch_bounds__(256) gather1_kernel(const float* __restrict__ b1) {
    int tt = blockIdx.x * blockDim.x + threadIdx.x;
    int node = tt >> 4;
    int sub  = tt & 15;
    if (node >= N_NODES) return;
    int s = d_ptr[node];
    int n = d_deg_i[node];

    float acc[8] = {};
    acc8(acc, reinterpret_cast<const uint4*>(d_g1 + (size_t)node * F_MID)[sub]);

    int i = 0;
    for (; i + 8 <= n; i += 8) {
        int r[8];
        #pragma unroll
        for (int j = 0; j < 8; j++) r[j] = d_csr[s + i + j];
        uint4 v[8];
        #pragma unroll
        for (int j = 0; j < 8; j++)
            v[j] = reinterpret_cast<const uint4*>(d_g1 + (size_t)r[j] * F_MID)[sub];
        #pragma unroll
        for (int j = 0; j < 8; j++) acc8(acc, v[j]);
    }
    for (; i < n; i++) {
        int r = d_csr[s + i];
        acc8(acc, reinterpret_cast<const uint4*>(d_g1 + (size_t)r * F_MID)[sub]);
    }

    float sc = d_dinv[node];
    float4 blo = reinterpret_cast<const float4*>(b1)[sub * 2];
    float4 bhi = reinterpret_cast<const float4*>(b1)[sub * 2 + 1];
    float o[8];
    o[0] = fmaxf(fmaf(acc[0], sc, blo.x), 0.0f);
    o[1] = fmaxf(fmaf(acc[1], sc, blo.y), 0.0f);
    o[2] = fmaxf(fmaf(acc[2], sc, blo.z), 0.0f);
    o[3] = fmaxf(fmaf(acc[3], sc, blo.w), 0.0f);
    o[4] = fmaxf(fmaf(acc[4], sc, bhi.x), 0.0f);
    o[5] = fmaxf(fmaf(acc[5], sc, bhi.y), 0.0f);
    o[6] = fmaxf(fmaf(acc[6], sc, bhi.z), 0.0f);
    o[7] = fmaxf(fmaf(acc[7], sc, bhi.w), 0.0f);

    uint4 ov;
    __half2* op = reinterpret_cast<__half2*>(&ov);
    op[0] = __floats2half2_rn(o[0], o[1]);
    op[1] = __floats2half2_rn(o[2], o[3]);
    op[2] = __floats2half2_rn(o[4], o[5]);
    op[3] = __floats2half2_rn(o[6], o[7]);
    reinterpret_cast<uint4*>(d_h + (size_t)node * F_MID)[sub] = ov;
}

// ---------------------------------------------------------------------------
// GEMM2 (tensor core): g2[i][:] = fp16((h[i][:] @ W2) * dinv[i])   (N = 64)
// ---------------------------------------------------------------------------
__global__ void __launch_bounds__(256) gemm2_tc() {
    int wid = threadIdx.x >> 5, lane = threadIdx.x & 31;
    int wg = blockIdx.x * 8 + wid;
    if (wg >= N_NODES / 16) return;
    int rb = wg * 16;
    int g = lane >> 2, t = lane & 3;
    const __half* arow0 = d_h + (size_t)(rb + g) * F_MID;
    const __half* arow8 = d_h + (size_t)(rb + g + 8) * F_MID;

    float c[8][4] = {};
    const uint2* Bf = reinterpret_cast<const uint2*>(d_w2f);

    #pragma unroll 4
    for (int ks = 0; ks < 16; ks++) {
        int k0 = ks * 8;
        uint32_t a0 = f2tf32(__half2float(arow0[k0 + t]));
        uint32_t a1 = f2tf32(__half2float(arow8[k0 + t]));
        uint32_t a2 = f2tf32(__half2float(arow0[k0 + t + 4]));
        uint32_t a3 = f2tf32(__half2float(arow8[k0 + t + 4]));
        #pragma unroll
        for (int nt = 0; nt < 8; nt++) {
            uint2 b = Bf[(ks * 8 + nt) * 32 + lane];
            mma_tf32(c[nt], a0, a1, a2, a3, b.x, b.y);
        }
    }

    float s0 = d_dinv[rb + g], s8 = d_dinv[rb + g + 8];
    __half2* o0 = reinterpret_cast<__half2*>(d_g2 + (size_t)(rb + g) * F_OUT);
    __half2* o8 = reinterpret_cast<__half2*>(d_g2 + (size_t)(rb + g + 8) * F_OUT);
    #pragma unroll
    for (int nt = 0; nt < 8; nt++) {
        int c2 = (nt * 8 + 2 * t) >> 1;
        o0[c2] = __floats2half2_rn(c[nt][0] * s0, c[nt][1] * s0);
        o8[c2] = __floats2half2_rn(c[nt][2] * s8, c[nt][3] * s8);
    }
}

// ---------------------------------------------------------------------------
// Gather layer 2: 8 threads per node (64 halves = 8 x uint4), unroll 8.
// ---------------------------------------------------------------------------
__global__ void __launch_bounds__(256) gather2_kernel(const float* __restrict__ b2,
                                                      float* __restrict__ out) {
    int tt = blockIdx.x * blockDim.x + threadIdx.x;
    int node = tt >> 3;
    int sub  = tt & 7;
    if (node >= N_NODES) return;
    int s = d_ptr[node];
    int n = d_deg_i[node];

    float acc[8] = {};
    acc8(acc, reinterpret_cast<const uint4*>(d_g2 + (size_t)node * F_OUT)[sub]);

    int i = 0;
    for (; i + 8 <= n; i += 8) {
        int r[8];
        #pragma unroll
        for (int j = 0; j < 8; j++) r[j] = d_csr[s + i + j];
        uint4 v[8];
        #pragma unroll
        for (int j = 0; j < 8; j++)
            v[j] = reinterpret_cast<const uint4*>(d_g2 + (size_t)r[j] * F_OUT)[sub];
        #pragma unroll
        for (int j = 0; j < 8; j++) acc8(acc, v[j]);
    }
    for (; i < n; i++) {
        int r = d_csr[s + i];
        acc8(acc, reinterpret_cast<const uint4*>(d_g2 + (size_t)r * F_OUT)[sub]);
    }

    float sc = d_dinv[node];
    float4 blo = reinterpret_cast<const float4*>(b2)[sub * 2];
    float4 bhi = reinterpret_cast<const float4*>(b2)[sub * 2 + 1];
    float4 olo, ohi;
    olo.x = fmaf(acc[0], sc, blo.x);
    olo.y = fmaf(acc[1], sc, blo.y);
    olo.z = fmaf(acc[2], sc, blo.z);
    olo.w = fmaf(acc[3], sc, blo.w);
    ohi.x = fmaf(acc[4], sc, bhi.x);
    ohi.y = fmaf(acc[5], sc, bhi.y);
    ohi.z = fmaf(acc[6], sc, bhi.z);
    ohi.w = fmaf(acc[7], sc, bhi.w);
    float4* orow = reinterpret_cast<float4*>(out + (size_t)node * F_OUT);
    orow[sub * 2]     = olo;
    orow[sub * 2 + 1] = ohi;
}

// ---------------------------------------------------------------------------
// Launch.  Inputs: x, edge_index(int32), edge_weight, W1, b1, W2, b2
// Two-stream overlap: side stream runs wf_prep + gemm1 while the main
// stream builds the CSR.  Streams/events are created lazily on the first
// (non-captured correctness) call and reused; the captured graph encodes
// the fork/join as dependencies.
// ---------------------------------------------------------------------------
static cudaStream_t g_sB = nullptr;
static cudaEvent_t  g_eFork = nullptr, g_eDinv = nullptr, g_eGemm1 = nullptr;

extern "C" void kernel_launch(void* const* d_in, const int* in_sizes, int n_in,
                              void* d_out, int out_size) {
    const float* x  = (const float*)d_in[0];
    const int*   ei = (const int*)d_in[1];
    const float* W1 = (const float*)d_in[3];
    const float* b1 = (const float*)d_in[4];
    const float* W2 = (const float*)d_in[5];
    const float* b2 = (const float*)d_in[6];
    float* out = (float*)d_out;

    if (!g_sB) {
        cudaStreamCreateWithFlags(&g_sB, cudaStreamNonBlocking);
        cudaEventCreateWithFlags(&g_eFork,  cudaEventDisableTiming);
        cudaEventCreateWithFlags(&g_eDinv,  cudaEventDisableTiming);
        cudaEventCreateWithFlags(&g_eGemm1, cudaEventDisableTiming);
    }

    const int nwarp_blocks = (N_NODES / 16 + 7) / 8;   // 782

    // Fork side stream off the (captured) legacy stream.
    cudaEventRecord(g_eFork, 0);
    cudaStreamWaitEvent(g_sB, g_eFork, 0);

    // Side stream: weight fragment prep (independent of everything).
    wf_prep_kernel<<<(16 * 16 * 32 + 16 * 8 * 32 + 255) / 256, 256, 0, g_sB>>>(W1, W2);

    // Main stream: degree -> dinv -> scan -> CSR fill.
    init_kernel<<<(N_NODES + 255) / 256, 256>>>();
    count_deg_kernel<<<(N_EDGES + 255) / 256, 256>>>(ei);
    dinv_kernel<<<(N_NODES + 255) / 256, 256>>>();
    cudaEventRecord(g_eDinv, 0);
    scan1_kernel<<<N_SCAN_BLKS, SCAN_BLK>>>();
    scan2_kernel<<<1, 256>>>();
    scan3_kernel<<<N_SCAN_BLKS, SCAN_BLK>>>();
    fill_csr_kernel<<<(N_EDGES + 255) / 256, 256>>>(ei);

    // Side stream: gemm1 once dinv is ready (overlaps scan+fill).
    cudaStreamWaitEvent(g_sB, g_eDinv, 0);
    gemm1_tc<<<nwarp_blocks, 256, 0, g_sB>>>(x);
    cudaEventRecord(g_eGemm1, g_sB);

    // Join: gather1 needs CSR (main-stream order) + g1 (event).
    cudaStreamWaitEvent(0, g_eGemm1, 0);
    gather1_kernel<<<(N_NODES * 16 + 255) / 256, 256>>>(b1);
    gemm2_tc<<<nwarp_blocks, 256>>>();
    gather2_kernel<<<(N_NODES * 8 + 255) / 256, 256>>>(b2, out);
}

// round 8
// speedup vs baseline: 2.8918x; 1.0635x over previous
#include <cuda_runtime.h>
#include <cuda_fp16.h>
#include <cstdint>

#define N_NODES 100000
#define N_EDGES 1600000
#define F_IN  128
#define F_MID 128
#define F_OUT 64

#define SCAN_BLK 512
#define N_SCAN_BLKS ((N_NODES + SCAN_BLK - 1) / SCAN_BLK)   // 196

// Scratch (static device globals; runtime allocation is forbidden)
__device__ __align__(16) int      d_deg_i[N_NODES];
__device__ __align__(16) int      d_fill [N_NODES];
__device__ __align__(16) int      d_ptr  [N_NODES];
__device__ __align__(16) int      d_bsum [N_SCAN_BLKS];
__device__ __align__(16) int      d_boff [N_SCAN_BLKS];
__device__ __align__(16) int      d_csr  [N_EDGES];
__device__ __align__(16) float    d_dinv [N_NODES];
__device__ __align__(16) __half   d_g1   [(size_t)N_NODES * F_MID];
__device__ __align__(16) __half   d_g2   [(size_t)N_NODES * F_OUT];
// W fragments in tf32, mma-fragment order: [kstep][ntile][lane][2]
__device__ __align__(16) uint32_t d_w1f  [16 * 16 * 32 * 2];   // 64KB
__device__ __align__(16) uint32_t d_w2f  [16 * 8  * 32 * 2];   // 32KB

// ---------------------------------------------------------------------------
// tf32 helpers
// ---------------------------------------------------------------------------
__device__ __forceinline__ uint32_t f2tf32(float f) {
    uint32_t r;
    asm("cvt.rna.tf32.f32 %0, %1;" : "=r"(r) : "f"(f));
    return r;
}

__device__ __forceinline__ void mma_tf32(float* c,
                                         uint32_t a0, uint32_t a1, uint32_t a2, uint32_t a3,
                                         uint32_t b0, uint32_t b1) {
    asm volatile("mma.sync.aligned.m16n8k8.row.col.f32.tf32.tf32.f32 "
                 "{%0,%1,%2,%3}, {%4,%5,%6,%7}, {%8,%9}, {%0,%1,%2,%3};"
                 : "+f"(c[0]), "+f"(c[1]), "+f"(c[2]), "+f"(c[3])
                 : "r"(a0), "r"(a1), "r"(a2), "r"(a3), "r"(b0), "r"(b1));
}

// Accumulate 8 halves (uint4) into 8 fp32 accumulators
__device__ __forceinline__ void acc8(float* acc, uint4 v) {
    const __half2* hp = reinterpret_cast<const __half2*>(&v);
    #pragma unroll
    for (int j = 0; j < 4; j++) {
        float2 f = __half22float2(hp[j]);
        acc[2 * j]     += f.x;
        acc[2 * j + 1] += f.y;
    }
}

// ---------------------------------------------------------------------------
// Degree / CSR build.  edge_index is int32 on device (JAX x64-disabled).
// ---------------------------------------------------------------------------
__global__ void init_kernel() {
    int i = blockIdx.x * blockDim.x + threadIdx.x;
    if (i < N_NODES) { d_deg_i[i] = 0; d_fill[i] = 0; }
}

__global__ void count_deg_kernel(const int* __restrict__ ei) {
    int e = blockIdx.x * blockDim.x + threadIdx.x;
    if (e < N_EDGES) atomicAdd(&d_deg_i[ei[N_EDGES + e]], 1);
}

__global__ void dinv_kernel() {
    int i = blockIdx.x * blockDim.x + threadIdx.x;
    if (i < N_NODES) d_dinv[i] = rsqrtf((float)(1 + d_deg_i[i]));
}

__global__ void scan1_kernel() {
    __shared__ int sm[SCAN_BLK];
    int tid = threadIdx.x;
    int i = blockIdx.x * SCAN_BLK + tid;
    int v = (i < N_NODES) ? d_deg_i[i] : 0;
    sm[tid] = v;
    __syncthreads();
    #pragma unroll
    for (int off = 1; off < SCAN_BLK; off <<= 1) {
        int t = (tid >= off) ? sm[tid - off] : 0;
        __syncthreads();
        if (tid >= off) sm[tid] += t;
        __syncthreads();
    }
    if (i < N_NODES) d_ptr[i] = sm[tid] - v;       // exclusive
    if (tid == SCAN_BLK - 1) d_bsum[blockIdx.x] = sm[tid];
}

__global__ void scan2_kernel() {
    __shared__ int sm[256];
    int tid = threadIdx.x;
    int v = (tid < N_SCAN_BLKS) ? d_bsum[tid] : 0;
    sm[tid] = v;
    __syncthreads();
    #pragma unroll
    for (int off = 1; off < 256; off <<= 1) {
        int t = (tid >= off) ? sm[tid - off] : 0;
        __syncthreads();
        if (tid >= off) sm[tid] += t;
        __syncthreads();
    }
    if (tid < N_SCAN_BLKS) d_boff[tid] = sm[tid] - v;  // exclusive
}

__global__ void scan3_kernel() {
    int i = blockIdx.x * SCAN_BLK + threadIdx.x;
    if (i < N_NODES) d_ptr[i] += d_boff[blockIdx.x];
}

__global__ void fill_csr_kernel(const int* __restrict__ ei) {
    int e = blockIdx.x * blockDim.x + threadIdx.x;
    if (e < N_EDGES) {
        int r = ei[e];
        int c = ei[N_EDGES + e];
        int slot = atomicAdd(&d_fill[c], 1);
        d_csr[d_ptr[c] + slot] = r;
    }
}

// ---------------------------------------------------------------------------
// W fragment prep (both weights in one kernel): tf32, mma B-fragment order.
// ---------------------------------------------------------------------------
__global__ void wf_prep_kernel(const float* __restrict__ W1,
                               const float* __restrict__ W2) {
    int i = blockIdx.x * blockDim.x + threadIdx.x;
    if (i < 16 * 16 * 32) {
        int lane = i & 31, nt = (i >> 5) & 15, ks = i >> 9;
        int g = lane >> 2, t = lane & 3;
        d_w1f[2 * i]     = f2tf32(W1[(ks * 8 + t)     * F_MID + nt * 8 + g]);
        d_w1f[2 * i + 1] = f2tf32(W1[(ks * 8 + t + 4) * F_MID + nt * 8 + g]);
    } else if (i < 16 * 16 * 32 + 16 * 8 * 32) {
        int j = i - 16 * 16 * 32;
        int lane = j & 31, nt = (j >> 5) & 7, ks = j >> 8;
        int g = lane >> 2, t = lane & 3;
        d_w2f[2 * j]     = f2tf32(W2[(ks * 8 + t)     * F_OUT + nt * 8 + g]);
        d_w2f[2 * j + 1] = f2tf32(W2[(ks * 8 + t + 4) * F_OUT + nt * 8 + g]);
    }
}

// ---------------------------------------------------------------------------
// GEMM1 (tensor core): g1[i][:] = fp16((x[i][:] @ W1) * dinv[i])
// ---------------------------------------------------------------------------
__global__ void __launch_bounds__(256) gemm1_tc(const float* __restrict__ x) {
    int wid = threadIdx.x >> 5, lane = threadIdx.x & 31;
    int wg = blockIdx.x * 8 + wid;
    if (wg >= N_NODES / 16) return;
    int rb = wg * 16;
    int g = lane >> 2, t = lane & 3;
    const float* arow0 = x + (size_t)(rb + g) * F_IN;
    const float* arow8 = x + (size_t)(rb + g + 8) * F_IN;

    float c[16][4] = {};
    const uint2* Bf = reinterpret_cast<const uint2*>(d_w1f);

    #pragma unroll 4
    for (int ks = 0; ks < 16; ks++) {
        int k0 = ks * 8;
        uint32_t a0 = f2tf32(arow0[k0 + t]);
        uint32_t a1 = f2tf32(arow8[k0 + t]);
        uint32_t a2 = f2tf32(arow0[k0 + t + 4]);
        uint32_t a3 = f2tf32(arow8[k0 + t + 4]);
        #pragma unroll
        for (int nt = 0; nt < 16; nt++) {
            uint2 b = Bf[(ks * 16 + nt) * 32 + lane];
            mma_tf32(c[nt], a0, a1, a2, a3, b.x, b.y);
        }
    }

    float s0 = d_dinv[rb + g], s8 = d_dinv[rb + g + 8];
    __half2* o0 = reinterpret_cast<__half2*>(d_g1 + (size_t)(rb + g) * F_MID);
    __half2* o8 = reinterpret_cast<__half2*>(d_g1 + (size_t)(rb + g + 8) * F_MID);
    #pragma unroll
    for (int nt = 0; nt < 16; nt++) {
        int c2 = (nt * 8 + 2 * t) >> 1;
        o0[c2] = __floats2half2_rn(c[nt][0] * s0, c[nt][1] * s0);
        o8[c2] = __floats2half2_rn(c[nt][2] * s8, c[nt][3] * s8);
    }
}

// ---------------------------------------------------------------------------
// FUSED gather1 + gemm2.
// Block = 256 threads handles 16 nodes (6250 blocks exactly).
//   Phase A (gather): 16 threads per node accumulate neighbor g1 rows,
//     apply dinv/bias/relu, stage the fp32 h row in smem (row pad 132).
//   Phase B (gemm2): warp w computes output cols [8w, 8w+8) for the block's
//     16-row tile via 16 m16n8k8 tf32 mmas; writes fp16 g2 * dinv.
// ---------------------------------------------------------------------------
__global__ void __launch_bounds__(256) gather1_gemm2_fused(const float* __restrict__ b1) {
    __shared__ float sh[16][132];   // 8.25KB, padded vs bank conflicts
    int tid = threadIdx.x;
    {
        int node16 = tid >> 4;
        int sub    = tid & 15;
        int node = blockIdx.x * 16 + node16;
        int s = d_ptr[node];
        int n = d_deg_i[node];

        float acc[8] = {};
        acc8(acc, reinterpret_cast<const uint4*>(d_g1 + (size_t)node * F_MID)[sub]);

        int i = 0;
        for (; i + 8 <= n; i += 8) {
            int r[8];
            #pragma unroll
            for (int j = 0; j < 8; j++) r[j] = d_csr[s + i + j];
            uint4 v[8];
            #pragma unroll
            for (int j = 0; j < 8; j++)
                v[j] = reinterpret_cast<const uint4*>(d_g1 + (size_t)r[j] * F_MID)[sub];
            #pragma unroll
            for (int j = 0; j < 8; j++) acc8(acc, v[j]);
        }
        for (; i < n; i++) {
            int r = d_csr[s + i];
            acc8(acc, reinterpret_cast<const uint4*>(d_g1 + (size_t)r * F_MID)[sub]);
        }

        float sc = d_dinv[node];
        float4 blo = reinterpret_cast<const float4*>(b1)[sub * 2];
        float4 bhi = reinterpret_cast<const float4*>(b1)[sub * 2 + 1];
        float* hrow = &sh[node16][sub * 8];
        hrow[0] = fmaxf(fmaf(acc[0], sc, blo.x), 0.0f);
        hrow[1] = fmaxf(fmaf(acc[1], sc, blo.y), 0.0f);
        hrow[2] = fmaxf(fmaf(acc[2], sc, blo.z), 0.0f);
        hrow[3] = fmaxf(fmaf(acc[3], sc, blo.w), 0.0f);
        hrow[4] = fmaxf(fmaf(acc[4], sc, bhi.x), 0.0f);
        hrow[5] = fmaxf(fmaf(acc[5], sc, bhi.y), 0.0f);
        hrow[6] = fmaxf(fmaf(acc[6], sc, bhi.z), 0.0f);
        hrow[7] = fmaxf(fmaf(acc[7], sc, bhi.w), 0.0f);
    }
    __syncthreads();

    // Phase B: gemm2 on the 16-row tile; warp w -> col tile nt = w.
    int wid = tid >> 5, lane = tid & 31;
    int g = lane >> 2, t = lane & 3;
    float c[4] = {};
    const uint2* Bf = reinterpret_cast<const uint2*>(d_w2f);

    #pragma unroll
    for (int ks = 0; ks < 16; ks++) {
        int k0 = ks * 8;
        uint32_t a0 = f2tf32(sh[g][k0 + t]);
        uint32_t a1 = f2tf32(sh[g + 8][k0 + t]);
        uint32_t a2 = f2tf32(sh[g][k0 + t + 4]);
        uint32_t a3 = f2tf32(sh[g + 8][k0 + t + 4]);
        uint2 b = Bf[(ks * 8 + wid) * 32 + lane];
        mma_tf32(c, a0, a1, a2, a3, b.x, b.y);
    }

    int row0 = blockIdx.x * 16 + g;
    int row8 = row0 + 8;
    float s0 = d_dinv[row0], s8 = d_dinv[row8];
    int c2 = (wid * 8 + 2 * t) >> 1;
    reinterpret_cast<__half2*>(d_g2 + (size_t)row0 * F_OUT)[c2] =
        __floats2half2_rn(c[0] * s0, c[1] * s0);
    reinterpret_cast<__half2*>(d_g2 + (size_t)row8 * F_OUT)[c2] =
        __floats2half2_rn(c[2] * s8, c[3] * s8);
}

// ---------------------------------------------------------------------------
// Gather layer 2: 8 threads per node (64 halves = 8 x uint4), unroll 8.
// ---------------------------------------------------------------------------
__global__ void __launch_bounds__(256) gather2_kernel(const float* __restrict__ b2,
                                                      float* __restrict__ out) {
    int tt = blockIdx.x * blockDim.x + threadIdx.x;
    int node = tt >> 3;
    int sub  = tt & 7;
    if (node >= N_NODES) return;
    int s = d_ptr[node];
    int n = d_deg_i[node];

    float acc[8] = {};
    acc8(acc, reinterpret_cast<const uint4*>(d_g2 + (size_t)node * F_OUT)[sub]);

    int i = 0;
    for (; i + 8 <= n; i += 8) {
        int r[8];
        #pragma unroll
        for (int j = 0; j < 8; j++) r[j] = d_csr[s + i + j];
        uint4 v[8];
        #pragma unroll
        for (int j = 0; j < 8; j++)
            v[j] = reinterpret_cast<const uint4*>(d_g2 + (size_t)r[j] * F_OUT)[sub];
        #pragma unroll
        for (int j = 0; j < 8; j++) acc8(acc, v[j]);
    }
    for (; i < n; i++) {
        int r = d_csr[s + i];
        acc8(acc, reinterpret_cast<const uint4*>(d_g2 + (size_t)r * F_OUT)[sub]);
    }

    float sc = d_dinv[node];
    float4 blo = reinterpret_cast<const float4*>(b2)[sub * 2];
    float4 bhi = reinterpret_cast<const float4*>(b2)[sub * 2 + 1];
    float4 olo, ohi;
    olo.x = fmaf(acc[0], sc, blo.x);
    olo.y = fmaf(acc[1], sc, blo.y);
    olo.z = fmaf(acc[2], sc, blo.z);
    olo.w = fmaf(acc[3], sc, blo.w);
    ohi.x = fmaf(acc[4], sc, bhi.x);
    ohi.y = fmaf(acc[5], sc, bhi.y);
    ohi.z = fmaf(acc[6], sc, bhi.z);
    ohi.w = fmaf(acc[7], sc, bhi.w);
    float4* orow = reinterpret_cast<float4*>(out + (size_t)node * F_OUT);
    orow[sub * 2]     = olo;
    orow[sub * 2 + 1] = ohi;
}

// ---------------------------------------------------------------------------
// Launch.  Inputs: x, edge_index(int32), edge_weight, W1, b1, W2, b2
// Two-stream overlap: side stream runs wf_prep + gemm1 while the main
// stream builds the CSR.
// ---------------------------------------------------------------------------
static cudaStream_t g_sB = nullptr;
static cudaEvent_t  g_eFork = nullptr, g_eDinv = nullptr, g_eGemm1 = nullptr;

extern "C" void kernel_launch(void* const* d_in, const int* in_sizes, int n_in,
                              void* d_out, int out_size) {
    const float* x  = (const float*)d_in[0];
    const int*   ei = (const int*)d_in[1];
    const float* W1 = (const float*)d_in[3];
    const float* b1 = (const float*)d_in[4];
    const float* W2 = (const float*)d_in[5];
    const float* b2 = (const float*)d_in[6];
    float* out = (float*)d_out;

    if (!g_sB) {
        cudaStreamCreateWithFlags(&g_sB, cudaStreamNonBlocking);
        cudaEventCreateWithFlags(&g_eFork,  cudaEventDisableTiming);
        cudaEventCreateWithFlags(&g_eDinv,  cudaEventDisableTiming);
        cudaEventCreateWithFlags(&g_eGemm1, cudaEventDisableTiming);
    }

    const int nwarp_blocks = (N_NODES / 16 + 7) / 8;   // 782

    // Fork side stream off the (captured) legacy stream.
    cudaEventRecord(g_eFork, 0);
    cudaStreamWaitEvent(g_sB, g_eFork, 0);

    // Side stream: weight fragment prep (independent of everything).
    wf_prep_kernel<<<(16 * 16 * 32 + 16 * 8 * 32 + 255) / 256, 256, 0, g_sB>>>(W1, W2);

    // Main stream: degree -> dinv -> scan -> CSR fill.
    init_kernel<<<(N_NODES + 255) / 256, 256>>>();
    count_deg_kernel<<<(N_EDGES + 255) / 256, 256>>>(ei);
    dinv_kernel<<<(N_NODES + 255) / 256, 256>>>();
    cudaEventRecord(g_eDinv, 0);
    scan1_kernel<<<N_SCAN_BLKS, SCAN_BLK>>>();
    scan2_kernel<<<1, 256>>>();
    scan3_kernel<<<N_SCAN_BLKS, SCAN_BLK>>>();
    fill_csr_kernel<<<(N_EDGES + 255) / 256, 256>>>(ei);

    // Side stream: gemm1 once dinv is ready (overlaps scan+fill).
    cudaStreamWaitEvent(g_sB, g_eDinv, 0);
    gemm1_tc<<<nwarp_blocks, 256, 0, g_sB>>>(x);
    cudaEventRecord(g_eGemm1, g_sB);

    // Join: fused gather1+gemm2 needs CSR (main-stream order) + g1 (event).
    cudaStreamWaitEvent(0, g_eGemm1, 0);
    gather1_gemm2_fused<<<N_NODES / 16, 256>>>(b1);
    gather2_kernel<<<(N_NODES * 8 + 255) / 256, 256>>>(b2, out);
}

// round 10
// speedup vs baseline: 3.1323x; 1.0832x over previous
#include <cuda_runtime.h>
#include <cuda_fp16.h>
#include <cstdint>

#define N_NODES 100000
#define N_EDGES 1600000
#define F_IN  128
#define F_MID 128
#define F_OUT 64

#define SCAN_BLK 512
#define N_SCAN_BLKS ((N_NODES + SCAN_BLK - 1) / SCAN_BLK)   // 196

// Scratch (static device globals; runtime allocation is forbidden)
__device__ __align__(16) int      d_deg_i[N_NODES];
__device__ __align__(16) int      d_fill [N_NODES];
__device__ __align__(16) int      d_ptr  [N_NODES];
__device__ __align__(16) int      d_bsum [N_SCAN_BLKS];
__device__ __align__(16) int      d_csr  [N_EDGES];
__device__ __align__(16) __half   d_g1   [(size_t)N_NODES * F_MID];
__device__ __align__(16) __half   d_g2   [(size_t)N_NODES * F_OUT];
// W fragments in tf32, mma-fragment order: [kstep][ntile][lane][2]
__device__ __align__(16) uint32_t d_w1f  [16 * 16 * 32 * 2];   // 64KB
__device__ __align__(16) uint32_t d_w2f  [16 * 8  * 32 * 2];   // 32KB

// ---------------------------------------------------------------------------
// helpers
// ---------------------------------------------------------------------------
__device__ __forceinline__ uint32_t f2tf32(float f) {
    uint32_t r;
    asm("cvt.rna.tf32.f32 %0, %1;" : "=r"(r) : "f"(f));
    return r;
}

__device__ __forceinline__ void mma_tf32(float* c,
                                         uint32_t a0, uint32_t a1, uint32_t a2, uint32_t a3,
                                         uint32_t b0, uint32_t b1) {
    asm volatile("mma.sync.aligned.m16n8k8.row.col.f32.tf32.tf32.f32 "
                 "{%0,%1,%2,%3}, {%4,%5,%6,%7}, {%8,%9}, {%0,%1,%2,%3};"
                 : "+f"(c[0]), "+f"(c[1]), "+f"(c[2]), "+f"(c[3])
                 : "r"(a0), "r"(a1), "r"(a2), "r"(a3), "r"(b0), "r"(b1));
}

__device__ __forceinline__ void acc8(float* acc, uint4 v) {
    const __half2* hp = reinterpret_cast<const __half2*>(&v);
    #pragma unroll
    for (int j = 0; j < 4; j++) {
        float2 f = __half22float2(hp[j]);
        acc[2 * j]     += f.x;
        acc[2 * j + 1] += f.y;
    }
}

// ---------------------------------------------------------------------------
// Degree / CSR build.  edge_index is int32 on device (JAX x64-disabled).
// ---------------------------------------------------------------------------
__global__ void init_kernel() {
    int i = blockIdx.x * blockDim.x + threadIdx.x;
    if (i < N_NODES) { d_deg_i[i] = 0; d_fill[i] = 0; }
}

// 2 edges per thread (N_EDGES is even; cols int2-aligned)
__global__ void count_deg_kernel(const int* __restrict__ ei) {
    int e2 = blockIdx.x * blockDim.x + threadIdx.x;
    if (e2 < N_EDGES / 2) {
        int2 c = reinterpret_cast<const int2*>(ei + N_EDGES)[e2];
        atomicAdd(&d_deg_i[c.x], 1);
        atomicAdd(&d_deg_i[c.y], 1);
    }
}

__global__ void scan1_kernel() {
    __shared__ int sm[SCAN_BLK];
    int tid = threadIdx.x;
    int i = blockIdx.x * SCAN_BLK + tid;
    int v = (i < N_NODES) ? d_deg_i[i] : 0;
    sm[tid] = v;
    __syncthreads();
    #pragma unroll
    for (int off = 1; off < SCAN_BLK; off <<= 1) {
        int t = (tid >= off) ? sm[tid - off] : 0;
        __syncthreads();
        if (tid >= off) sm[tid] += t;
        __syncthreads();
    }
    if (i < N_NODES) d_ptr[i] = sm[tid] - v;       // exclusive
    if (tid == SCAN_BLK - 1) d_bsum[blockIdx.x] = sm[tid];
}

// merged scan2+scan3: each block reduces its own d_bsum prefix, then adds.
__global__ void scan3_kernel() {
    __shared__ int red[SCAN_BLK];
    int tid = threadIdx.x;
    int acc = 0;
    for (int j = tid; j < blockIdx.x; j += SCAN_BLK) acc += d_bsum[j];
    red[tid] = acc;
    __syncthreads();
    #pragma unroll
    for (int off = SCAN_BLK / 2; off > 0; off >>= 1) {
        if (tid < off) red[tid] += red[tid + off];
        __syncthreads();
    }
    int boff = red[0];
    int i = blockIdx.x * SCAN_BLK + tid;
    if (i < N_NODES) d_ptr[i] += boff;
}

__global__ void fill_csr_kernel(const int* __restrict__ ei) {
    int e = blockIdx.x * blockDim.x + threadIdx.x;
    if (e < N_EDGES) {
        int r = ei[e];
        int c = ei[N_EDGES + e];
        int slot = atomicAdd(&d_fill[c], 1);
        d_csr[d_ptr[c] + slot] = r;
    }
}

// ---------------------------------------------------------------------------
// W fragment prep: tf32, mma B-fragment order.
// ---------------------------------------------------------------------------
__global__ void wf_prep_kernel(const float* __restrict__ W1,
                               const float* __restrict__ W2) {
    int i = blockIdx.x * blockDim.x + threadIdx.x;
    if (i < 16 * 16 * 32) {
        int lane = i & 31, nt = (i >> 5) & 15, ks = i >> 9;
        int g = lane >> 2, t = lane & 3;
        d_w1f[2 * i]     = f2tf32(W1[(ks * 8 + t)     * F_MID + nt * 8 + g]);
        d_w1f[2 * i + 1] = f2tf32(W1[(ks * 8 + t + 4) * F_MID + nt * 8 + g]);
    } else if (i < 16 * 16 * 32 + 16 * 8 * 32) {
        int j = i - 16 * 16 * 32;
        int lane = j & 31, nt = (j >> 5) & 7, ks = j >> 8;
        int g = lane >> 2, t = lane & 3;
        d_w2f[2 * j]     = f2tf32(W2[(ks * 8 + t)     * F_OUT + nt * 8 + g]);
        d_w2f[2 * j + 1] = f2tf32(W2[(ks * 8 + t + 4) * F_OUT + nt * 8 + g]);
    }
}

// ---------------------------------------------------------------------------
// GEMM1 (tensor core): g1[i][:] = fp16((x[i][:] @ W1) * dinv[i])
// Each warp: 16 rows x 128 cols.  A tile staged in smem via coalesced
// float4 loads (132-float row pad => conflict-free fragment LDS).
// Dynamic smem: 8 warps * 16 * 132 * 4B = 67584B.
// ---------------------------------------------------------------------------
__global__ void __launch_bounds__(256) gemm1_tc(const float* __restrict__ x) {
    extern __shared__ float xs[];   // [8][16][132]
    int wid = threadIdx.x >> 5, lane = threadIdx.x & 31;
    int wg = blockIdx.x * 8 + wid;
    if (wg >= N_NODES / 16) return;
    int rb = wg * 16;
    float* xt = xs + wid * (16 * 132);

    // Stage A: one float4 per row per lane (16 rows)
    #pragma unroll
    for (int r = 0; r < 16; r++) {
        float4 v = reinterpret_cast<const float4*>(x + (size_t)(rb + r) * F_IN)[lane];
        *reinterpret_cast<float4*>(&xt[r * 132 + lane * 4]) = v;
    }
    __syncwarp();

    int g = lane >> 2, t = lane & 3;
    const float* a0p = &xt[g * 132];
    const float* a8p = &xt[(g + 8) * 132];

    float c[16][4] = {};
    const uint2* Bf = reinterpret_cast<const uint2*>(d_w1f);

    #pragma unroll 4
    for (int ks = 0; ks < 16; ks++) {
        int k0 = ks * 8;
        uint32_t a0 = f2tf32(a0p[k0 + t]);
        uint32_t a1 = f2tf32(a8p[k0 + t]);
        uint32_t a2 = f2tf32(a0p[k0 + t + 4]);
        uint32_t a3 = f2tf32(a8p[k0 + t + 4]);
        #pragma unroll
        for (int nt = 0; nt < 16; nt++) {
            uint2 b = Bf[(ks * 16 + nt) * 32 + lane];
            mma_tf32(c[nt], a0, a1, a2, a3, b.x, b.y);
        }
    }

    float s0 = rsqrtf((float)(1 + d_deg_i[rb + g]));
    float s8 = rsqrtf((float)(1 + d_deg_i[rb + g + 8]));
    __half2* o0 = reinterpret_cast<__half2*>(d_g1 + (size_t)(rb + g) * F_MID);
    __half2* o8 = reinterpret_cast<__half2*>(d_g1 + (size_t)(rb + g + 8) * F_MID);
    #pragma unroll
    for (int nt = 0; nt < 16; nt++) {
        int c2 = (nt * 8 + 2 * t) >> 1;
        o0[c2] = __floats2half2_rn(c[nt][0] * s0, c[nt][1] * s0);
        o8[c2] = __floats2half2_rn(c[nt][2] * s8, c[nt][3] * s8);
    }
}

// ---------------------------------------------------------------------------
// FUSED gather1 + gemm2.  Block = 256 threads = 16 nodes (6250 blocks).
// ---------------------------------------------------------------------------
__global__ void __launch_bounds__(256) gather1_gemm2_fused(const float* __restrict__ b1) {
    __shared__ float sh[16][132];
    int tid = threadIdx.x;
    {
        int node16 = tid >> 4;
        int sub    = tid & 15;
        int node = blockIdx.x * 16 + node16;
        int s = d_ptr[node];
        int n = d_deg_i[node];

        float acc[8] = {};
        acc8(acc, reinterpret_cast<const uint4*>(d_g1 + (size_t)node * F_MID)[sub]);

        int i = 0;
        for (; i + 8 <= n; i += 8) {
            int r[8];
            #pragma unroll
            for (int j = 0; j < 8; j++) r[j] = d_csr[s + i + j];
            uint4 v[8];
            #pragma unroll
            for (int j = 0; j < 8; j++)
                v[j] = reinterpret_cast<const uint4*>(d_g1 + (size_t)r[j] * F_MID)[sub];
            #pragma unroll
            for (int j = 0; j < 8; j++) acc8(acc, v[j]);
        }
        for (; i < n; i++) {
            int r = d_csr[s + i];
            acc8(acc, reinterpret_cast<const uint4*>(d_g1 + (size_t)r * F_MID)[sub]);
        }

        float sc = rsqrtf((float)(1 + n));
        float4 blo = reinterpret_cast<const float4*>(b1)[sub * 2];
        float4 bhi = reinterpret_cast<const float4*>(b1)[sub * 2 + 1];
        float* hrow = &sh[node16][sub * 8];
        hrow[0] = fmaxf(fmaf(acc[0], sc, blo.x), 0.0f);
        hrow[1] = fmaxf(fmaf(acc[1], sc, blo.y), 0.0f);
        hrow[2] = fmaxf(fmaf(acc[2], sc, blo.z), 0.0f);
        hrow[3] = fmaxf(fmaf(acc[3], sc, blo.w), 0.0f);
        hrow[4] = fmaxf(fmaf(acc[4], sc, bhi.x), 0.0f);
        hrow[5] = fmaxf(fmaf(acc[5], sc, bhi.y), 0.0f);
        hrow[6] = fmaxf(fmaf(acc[6], sc, bhi.z), 0.0f);
        hrow[7] = fmaxf(fmaf(acc[7], sc, bhi.w), 0.0f);
    }
    __syncthreads();

    // Phase B: gemm2; warp w -> col tile nt = w.
    int wid = tid >> 5, lane = tid & 31;
    int g = lane >> 2, t = lane & 3;
    float c[4] = {};
    const uint2* Bf = reinterpret_cast<const uint2*>(d_w2f);

    #pragma unroll
    for (int ks = 0; ks < 16; ks++) {
        int k0 = ks * 8;
        uint32_t a0 = f2tf32(sh[g][k0 + t]);
        uint32_t a1 = f2tf32(sh[g + 8][k0 + t]);
        uint32_t a2 = f2tf32(sh[g][k0 + t + 4]);
        uint32_t a3 = f2tf32(sh[g + 8][k0 + t + 4]);
        uint2 b = Bf[(ks * 8 + wid) * 32 + lane];
        mma_tf32(c, a0, a1, a2, a3, b.x, b.y);
    }

    int row0 = blockIdx.x * 16 + g;
    int row8 = row0 + 8;
    float s0 = rsqrtf((float)(1 + d_deg_i[row0]));
    float s8 = rsqrtf((float)(1 + d_deg_i[row8]));
    int c2 = (wid * 8 + 2 * t) >> 1;
    reinterpret_cast<__half2*>(d_g2 + (size_t)row0 * F_OUT)[c2] =
        __floats2half2_rn(c[0] * s0, c[1] * s0);
    reinterpret_cast<__half2*>(d_g2 + (size_t)row8 * F_OUT)[c2] =
        __floats2half2_rn(c[2] * s8, c[3] * s8);
}

// ---------------------------------------------------------------------------
// Gather layer 2: 8 threads per node, unroll 8.
// ---------------------------------------------------------------------------
__global__ void __launch_bounds__(256) gather2_kernel(const float* __restrict__ b2,
                                                      float* __restrict__ out) {
    int tt = blockIdx.x * blockDim.x + threadIdx.x;
    int node = tt >> 3;
    int sub  = tt & 7;
    if (node >= N_NODES) return;
    int s = d_ptr[node];
    int n = d_deg_i[node];

    float acc[8] = {};
    acc8(acc, reinterpret_cast<const uint4*>(d_g2 + (size_t)node * F_OUT)[sub]);

    int i = 0;
    for (; i + 8 <= n; i += 8) {
        int r[8];
        #pragma unroll
        for (int j = 0; j < 8; j++) r[j] = d_csr[s + i + j];
        uint4 v[8];
        #pragma unroll
        for (int j = 0; j < 8; j++)
            v[j] = reinterpret_cast<const uint4*>(d_g2 + (size_t)r[j] * F_OUT)[sub];
        #pragma unroll
        for (int j = 0; j < 8; j++) acc8(acc, v[j]);
    }
    for (; i < n; i++) {
        int r = d_csr[s + i];
        acc8(acc, reinterpret_cast<const uint4*>(d_g2 + (size_t)r * F_OUT)[sub]);
    }

    float sc = rsqrtf((float)(1 + n));
    float4 blo = reinterpret_cast<const float4*>(b2)[sub * 2];
    float4 bhi = reinterpret_cast<const float4*>(b2)[sub * 2 + 1];
    float4 olo, ohi;
    olo.x = fmaf(acc[0], sc, blo.x);
    olo.y = fmaf(acc[1], sc, blo.y);
    olo.z = fmaf(acc[2], sc, blo.z);
    olo.w = fmaf(acc[3], sc, blo.w);
    ohi.x = fmaf(acc[4], sc, bhi.x);
    ohi.y = fmaf(acc[5], sc, bhi.y);
    ohi.z = fmaf(acc[6], sc, bhi.z);
    ohi.w = fmaf(acc[7], sc, bhi.w);
    float4* orow = reinterpret_cast<float4*>(out + (size_t)node * F_OUT);
    orow[sub * 2]     = olo;
    orow[sub * 2 + 1] = ohi;
}

// ---------------------------------------------------------------------------
// Launch.  Inputs: x, edge_index(int32), edge_weight, W1, b1, W2, b2
// ---------------------------------------------------------------------------
static cudaStream_t g_sB = nullptr;
static cudaEvent_t  g_eFork = nullptr, g_eDeg = nullptr, g_eGemm1 = nullptr;

#define GEMM1_SMEM (8 * 16 * 132 * 4)

extern "C" void kernel_launch(void* const* d_in, const int* in_sizes, int n_in,
                              void* d_out, int out_size) {
    const float* x  = (const float*)d_in[0];
    const int*   ei = (const int*)d_in[1];
    const float* W1 = (const float*)d_in[3];
    const float* b1 = (const float*)d_in[4];
    const float* W2 = (const float*)d_in[5];
    const float* b2 = (const float*)d_in[6];
    float* out = (float*)d_out;

    if (!g_sB) {
        cudaStreamCreateWithFlags(&g_sB, cudaStreamNonBlocking);
        cudaEventCreateWithFlags(&g_eFork,  cudaEventDisableTiming);
        cudaEventCreateWithFlags(&g_eDeg,   cudaEventDisableTiming);
        cudaEventCreateWithFlags(&g_eGemm1, cudaEventDisableTiming);
        cudaFuncSetAttribute(gemm1_tc, cudaFuncAttributeMaxDynamicSharedMemorySize,
                             GEMM1_SMEM);
    }

    const int nwarp_blocks = (N_NODES / 16 + 7) / 8;   // 782

    // Fork side stream off the (captured) legacy stream.
    cudaEventRecord(g_eFork, 0);
    cudaStreamWaitEvent(g_sB, g_eFork, 0);

    // Side stream: weight fragment prep.
    wf_prep_kernel<<<(16 * 16 * 32 + 16 * 8 * 32 + 255) / 256, 256, 0, g_sB>>>(W1, W2);

    // Main stream: degree -> scan -> CSR fill.
    init_kernel<<<(N_NODES + 255) / 256, 256>>>();
    count_deg_kernel<<<(N_EDGES / 2 + 255) / 256, 256>>>(ei);
    cudaEventRecord(g_eDeg, 0);
    scan1_kernel<<<N_SCAN_BLKS, SCAN_BLK>>>();
    scan3_kernel<<<N_SCAN_BLKS, SCAN_BLK>>>();
    fill_csr_kernel<<<(N_EDGES + 255) / 256, 256>>>(ei);

    // Side stream: gemm1 once degrees are ready (overlaps scan+fill).
    cudaStreamWaitEvent(g_sB, g_eDeg, 0);
    gemm1_tc<<<nwarp_blocks, 256, GEMM1_SMEM, g_sB>>>(x);
    cudaEventRecord(g_eGemm1, g_sB);

    // Join: fused gather1+gemm2 needs CSR (main-stream order) + g1 (event).
    cudaStreamWaitEvent(0, g_eGemm1, 0);
    gather1_gemm2_fused<<<N_NODES / 16, 256>>>(b1);
    gather2_kernel<<<(N_NODES * 8 + 255) / 256, 256>>>(b2, out);
}